// round 5
// baseline (speedup 1.0000x reference)
#include <cuda_runtime.h>
#include <cuda_bf16.h>
#include <cstdint>

// Shapes (fixed): z (16,256,32,32) fp32; codebook (2048,256) fp32; out like z.
#define N_ROWS 16384
#define DDIM   256
#define KCODES 2048
#define HW     1024

// ---------------- device scratch (no mallocs allowed) ----------------
__device__ float         g_cnorm[KCODES];
__device__ float         g_znorm[N_ROWS];
__device__ int           g_bestIdx[N_ROWS];
__device__ float         g_zt [N_ROWS * DDIM];        // token-major fp32 z (exact copy)
__device__ __nv_bfloat16 g_ztb[N_ROWS * DDIM];        // token-major bf16 z
__device__ __nv_bfloat16 g_cbb[KCODES * DDIM];        // bf16 codebook
__device__ uint32_t      g_S  [N_ROWS * KCODES / 2];  // coarse dots, bf16 pairs

// pack 2 fp32 -> bf16x2 (result: lo = a, hi = b)
__device__ __forceinline__ uint32_t cvt_bf16x2(float a, float b) {
    uint32_t r;
    asm("cvt.rn.bf16x2.f32 %0, %1, %2;" : "=r"(r) : "f"(b), "f"(a));
    return r;
}

// ---------------- exact-chain norms (identical to R2, which matched JAX) ----
__global__ void cnorm_kernel(const float* __restrict__ cb) {
    int k = blockIdx.x * blockDim.x + threadIdx.x;
    if (k >= KCODES) return;
    const float* row = cb + (size_t)k * DDIM;
    float s = 0.f;
    #pragma unroll 8
    for (int d = 0; d < DDIM; d++) s = __fmaf_rn(row[d], row[d], s);
    g_cnorm[k] = s;
}
__global__ void znorm_kernel(const float* __restrict__ z) {
    int n = blockIdx.x * blockDim.x + threadIdx.x;
    if (n >= N_ROWS) return;
    int b = n >> 10, p = n & 1023;
    const float* zp = z + (size_t)b * DDIM * HW + p;
    float s = 0.f;
    #pragma unroll 8
    for (int d = 0; d < DDIM; d++) { float v = zp[(size_t)d * HW]; s = __fmaf_rn(v, v, s); }
    g_znorm[n] = s;
}

// ---------------- transpose z -> token-major fp32 + bf16 ----------------
__global__ void transpose_kernel(const float* __restrict__ z) {
    __shared__ float ts[32][33];
    int t = threadIdx.x, tx = t & 31, ty = t >> 5;   // 32 x 8
    int pt = blockIdx.x & 31, dt = blockIdx.x >> 5;  // 32 p-tiles, 8 d-tiles
    int b  = blockIdx.y;
    int p0 = pt * 32, d0 = dt * 32;
    #pragma unroll
    for (int i = 0; i < 4; i++) {
        int d = d0 + ty + i * 8;
        ts[ty + i * 8][tx] = z[((size_t)(b * DDIM + d)) * HW + p0 + tx];
    }
    __syncthreads();
    #pragma unroll
    for (int i = 0; i < 4; i++) {
        int n = b * HW + p0 + ty + i * 8;
        float v = ts[tx][ty + i * 8];
        g_zt [(size_t)n * DDIM + d0 + tx] = v;
        g_ztb[(size_t)n * DDIM + d0 + tx] = __float2bfloat16(v);
    }
}
__global__ void cbconv_kernel(const float* __restrict__ cb) {
    int i = blockIdx.x * blockDim.x + threadIdx.x;
    g_cbb[i] = __float2bfloat16(cb[i]);
}

// ---------------- coarse GEMM: S = Zb @ Cb^T via mma.sync bf16 (HMMA) -------
// CTA: 128 tokens x 128 codes. 8 warps as 4(m) x 2(n); warp tile 32 x 64.
// K = 256 staged in 4 chunks of 64 halves. Smem pitch 72 halves (144 B = 4
// banks mod 32) -> conflict-free fragment loads.
#define PITCH 72

__device__ __forceinline__ void mma16816(float* c, uint32_t a0, uint32_t a1,
                                         uint32_t a2, uint32_t a3,
                                         uint32_t b0, uint32_t b1) {
    asm volatile(
        "mma.sync.aligned.m16n8k16.row.col.f32.bf16.bf16.f32 "
        "{%0,%1,%2,%3}, {%4,%5,%6,%7}, {%8,%9}, {%0,%1,%2,%3};"
        : "+f"(c[0]), "+f"(c[1]), "+f"(c[2]), "+f"(c[3])
        : "r"(a0), "r"(a1), "r"(a2), "r"(a3), "r"(b0), "r"(b1));
}

__global__ void __launch_bounds__(256, 2) mma_kernel() {
    __shared__ __align__(16) __nv_bfloat16 As[128 * PITCH];
    __shared__ __align__(16) __nv_bfloat16 Bs[128 * PITCH];

    const int t = threadIdx.x, wid = t >> 5, lane = t & 31;
    const int row0 = blockIdx.x * 128, col0 = blockIdx.y * 128;
    const int wm = (wid & 3) * 32;        // warp m-offset in tile
    const int wn = (wid >> 2) * 64;       // warp n-offset in tile
    const int r  = lane >> 2;             // 0..7
    const int tt = lane & 3;              // 0..3

    float acc[2][8][4];
    #pragma unroll
    for (int mt = 0; mt < 2; mt++)
        #pragma unroll
        for (int nt = 0; nt < 8; nt++)
            #pragma unroll
            for (int q = 0; q < 4; q++) acc[mt][nt][q] = 0.f;

    for (int ch = 0; ch < 4; ch++) {
        const int cd0 = ch * 64;
        // stage A and B chunks: 128 rows x 64 halves each, uint4 = 8 halves
        #pragma unroll
        for (int it = 0; it < 4; it++) {
            int idx = it * 256 + t;            // 0..1023
            int rr = idx >> 3, k8 = (idx & 7) * 8;
            *reinterpret_cast<uint4*>(&As[rr * PITCH + k8]) =
                *reinterpret_cast<const uint4*>(&g_ztb[(size_t)(row0 + rr) * DDIM + cd0 + k8]);
            *reinterpret_cast<uint4*>(&Bs[rr * PITCH + k8]) =
                *reinterpret_cast<const uint4*>(&g_cbb[(size_t)(col0 + rr) * DDIM + cd0 + k8]);
        }
        __syncthreads();

        #pragma unroll
        for (int ks = 0; ks < 4; ks++) {       // four k16 steps per chunk
            const int k0 = ks * 16;
            #pragma unroll
            for (int mt = 0; mt < 2; mt++) {
                const __nv_bfloat16* ap = &As[(wm + mt * 16 + r) * PITCH + k0 + tt * 2];
                uint32_t a0 = *reinterpret_cast<const uint32_t*>(ap);
                uint32_t a2 = *reinterpret_cast<const uint32_t*>(ap + 8);
                uint32_t a1 = *reinterpret_cast<const uint32_t*>(ap + 8 * PITCH);
                uint32_t a3 = *reinterpret_cast<const uint32_t*>(ap + 8 * PITCH + 8);
                #pragma unroll
                for (int nt = 0; nt < 8; nt++) {
                    const __nv_bfloat16* bp = &Bs[(wn + nt * 8 + r) * PITCH + k0 + tt * 2];
                    uint32_t b0 = *reinterpret_cast<const uint32_t*>(bp);
                    uint32_t b1 = *reinterpret_cast<const uint32_t*>(bp + 8);
                    mma16816(acc[mt][nt], a0, a1, a2, a3, b0, b1);
                }
            }
        }
        __syncthreads();
    }

    // epilogue: c0/c1 = (row, col 2t / 2t+1), c2/c3 = row+8 -> bf16x2 stores
    #pragma unroll
    for (int mt = 0; mt < 2; mt++) {
        #pragma unroll
        for (int nt = 0; nt < 8; nt++) {
            int grow = row0 + wm + mt * 16 + r;
            int gcolp = (col0 + wn + nt * 8) / 2 + tt;    // u32 (pair) column
            g_S[(size_t)grow * (KCODES / 2) + gcolp] =
                cvt_bf16x2(acc[mt][nt][0], acc[mt][nt][1]);
            g_S[(size_t)(grow + 8) * (KCODES / 2) + gcolp] =
                cvt_bf16x2(acc[mt][nt][2], acc[mt][nt][3]);
        }
    }
}

// ---------------- scan: coarse min + margin rescan + exact rescore ----------
#define MARGIN 8e-3f

__global__ void __launch_bounds__(256) scan_kernel(const float* __restrict__ cb) {
    int n = (blockIdx.x * blockDim.x + threadIdx.x) >> 5;   // token (warp per token)
    int lane = threadIdx.x & 31;
    const uint32_t* srow = g_S + (size_t)n * (KCODES / 2);
    float zn = g_znorm[n];

    // phase 1: coarse min of (cnorm - 2*dot)
    float m = 3.4e38f;
    #pragma unroll 4
    for (int it = 0; it < 32; it++) {
        int j = it * 32 + lane;                 // u32 index -> codes 2j, 2j+1
        uint32_t v = srow[j];
        __nv_bfloat162 bb = *reinterpret_cast<__nv_bfloat162*>(&v);
        float c0 = __fmaf_rn(-2.0f, __bfloat162float(bb.x), g_cnorm[2 * j]);
        float c1 = __fmaf_rn(-2.0f, __bfloat162float(bb.y), g_cnorm[2 * j + 1]);
        m = fminf(m, fminf(c0, c1));
    }
    #pragma unroll
    for (int off = 16; off; off >>= 1)
        m = fminf(m, __shfl_xor_sync(0xffffffffu, m, off));
    float thresh = m + MARGIN;

    // phase 2: exact rescore of candidates (identical fp32 chain as R2)
    unsigned long long best = 0xffffffffffffffffull;
    for (int it = 0; it < 32; it++) {
        int j = it * 32 + lane;
        uint32_t v = srow[j];
        __nv_bfloat162 bb = *reinterpret_cast<__nv_bfloat162*>(&v);
        #pragma unroll
        for (int h = 0; h < 2; h++) {
            float cv = __fmaf_rn(-2.0f, (h ? __bfloat162float(bb.y) : __bfloat162float(bb.x)),
                                 g_cnorm[2 * j + h]);
            if (cv <= thresh) {
                int k = 2 * j + h;
                const float* za = g_zt + (size_t)n * DDIM;
                const float* ca = cb + (size_t)k * DDIM;
                float acc = 0.f;
                #pragma unroll 8
                for (int d = 0; d < DDIM; d++) acc = __fmaf_rn(za[d], ca[d], acc);
                float dist = __fadd_rn(__fadd_rn(zn, g_cnorm[k]), -2.0f * acc);
                unsigned long long pk =
                    ((unsigned long long)__float_as_uint(dist) << 32) | (unsigned)k;
                if (pk < best) best = pk;
            }
        }
    }
    #pragma unroll
    for (int off = 16; off; off >>= 1) {
        unsigned long long o = __shfl_xor_sync(0xffffffffu, best, off);
        if (o < best) best = o;
    }
    if (lane == 0) g_bestIdx[n] = (int)(best & 0xffffffffu);
}

// ---------------- gather + STE (unchanged, matched twice) ----------------
__global__ void gather_kernel(const float* __restrict__ z,
                              const float* __restrict__ cb,
                              float* __restrict__ out) {
    int o4 = blockIdx.x * blockDim.x + threadIdx.x;
    int p4 = o4 & 255, d = (o4 >> 8) & 255, b = o4 >> 16;
    int p = p4 * 4, nb = b * HW + p;
    size_t off = ((size_t)(b * DDIM + d)) * HW + p;
    float4 zv = *reinterpret_cast<const float4*>(z + off);
    float q0 = cb[(size_t)g_bestIdx[nb + 0] * DDIM + d];
    float q1 = cb[(size_t)g_bestIdx[nb + 1] * DDIM + d];
    float q2 = cb[(size_t)g_bestIdx[nb + 2] * DDIM + d];
    float q3 = cb[(size_t)g_bestIdx[nb + 3] * DDIM + d];
    float4 r;
    r.x = __fadd_rn(zv.x, __fadd_rn(q0, -zv.x));
    r.y = __fadd_rn(zv.y, __fadd_rn(q1, -zv.y));
    r.z = __fadd_rn(zv.z, __fadd_rn(q2, -zv.z));
    r.w = __fadd_rn(zv.w, __fadd_rn(q3, -zv.w));
    *reinterpret_cast<float4*>(out + off) = r;
}

// ---------------------------------------------------------------------------
extern "C" void kernel_launch(void* const* d_in, const int* in_sizes, int n_in,
                              void* d_out, int out_size) {
    const float* z  = (const float*)d_in[0];
    const float* cb = (const float*)d_in[1];
    float* out = (float*)d_out;

    transpose_kernel<<<dim3(256, 16), 256>>>(z);
    cbconv_kernel<<<(KCODES * DDIM) / 256, 256>>>(cb);
    cnorm_kernel<<<KCODES / 256, 256>>>(cb);
    znorm_kernel<<<N_ROWS / 256, 256>>>(z);
    mma_kernel<<<dim3(N_ROWS / 128, KCODES / 128), 256>>>();
    scan_kernel<<<(N_ROWS * 32) / 256, 256>>>(cb);
    gather_kernel<<<(N_ROWS * DDIM / 4) / 256, 256>>>(z, cb, out);
}

// round 6
// speedup vs baseline: 1.2332x; 1.2332x over previous
#include <cuda_runtime.h>
#include <cuda_bf16.h>
#include <cstdint>

// Shapes (fixed): z (16,256,32,32) fp32; codebook (2048,256) fp32; out like z.
#define N_ROWS 16384
#define DDIM   256
#define KCODES 2048
#define HW     1024

// ---------------- device scratch (no mallocs allowed) ----------------
__device__ float         g_cnorm[KCODES];
__device__ float         g_znorm[N_ROWS];
__device__ uint32_t      g_minu[N_ROWS];              // monotonic-mapped coarse row min
__device__ int           g_bestIdx[N_ROWS];
__device__ float         g_zt [N_ROWS * DDIM];        // token-major fp32 z (exact copy)
__device__ __nv_bfloat16 g_ztb[N_ROWS * DDIM];        // token-major bf16 z
__device__ __nv_bfloat16 g_cbb[KCODES * DDIM];        // bf16 codebook
__device__ uint32_t      g_S  [N_ROWS * KCODES / 2];  // coarse dists, bf16 pairs

// ---------------- small helpers ----------------
// pack 2 fp32 -> bf16x2 (result: lo = a, hi = b)
__device__ __forceinline__ uint32_t cvt_bf16x2(float a, float b) {
    uint32_t r;
    asm("cvt.rn.bf16x2.f32 %0, %1, %2;" : "=r"(r) : "f"(b), "f"(a));
    return r;
}
// order-preserving float -> uint32 map (for atomicMin) and inverse
__device__ __forceinline__ uint32_t fmap(float f) {
    uint32_t b = __float_as_uint(f);
    return (b & 0x80000000u) ? ~b : (b | 0x80000000u);
}
__device__ __forceinline__ float funmap(uint32_t u) {
    uint32_t b = (u & 0x80000000u) ? (u & 0x7fffffffu) : ~u;
    return __uint_as_float(b);
}
__device__ __forceinline__ void ldsm4(uint32_t& r0, uint32_t& r1, uint32_t& r2,
                                      uint32_t& r3, uint32_t addr) {
    asm volatile("ldmatrix.sync.aligned.m8n8.x4.shared.b16 {%0,%1,%2,%3}, [%4];"
                 : "=r"(r0), "=r"(r1), "=r"(r2), "=r"(r3) : "r"(addr));
}
__device__ __forceinline__ uint32_t smem_u32(const void* p) {
    uint32_t a;
    asm("{ .reg .u64 t; cvta.to.shared.u64 t, %1; cvt.u32.u64 %0, t; }" : "=r"(a) : "l"(p));
    return a;
}
__device__ __forceinline__ void mma16816(float* c, uint32_t a0, uint32_t a1,
                                         uint32_t a2, uint32_t a3,
                                         uint32_t b0, uint32_t b1) {
    asm volatile(
        "mma.sync.aligned.m16n8k16.row.col.f32.bf16.bf16.f32 "
        "{%0,%1,%2,%3}, {%4,%5,%6,%7}, {%8,%9}, {%0,%1,%2,%3};"
        : "+f"(c[0]), "+f"(c[1]), "+f"(c[2]), "+f"(c[3])
        : "r"(a0), "r"(a1), "r"(a2), "r"(a3), "r"(b0), "r"(b1));
}

// ---------------- (1) codebook: bf16 convert + exact sequential cnorm -------
__global__ void cbcnorm_kernel(const float* __restrict__ cb) {
    int k = blockIdx.x * blockDim.x + threadIdx.x;
    if (k >= KCODES) return;
    const float4* row4 = reinterpret_cast<const float4*>(cb + (size_t)k * DDIM);
    uint32_t* out = reinterpret_cast<uint32_t*>(g_cbb + (size_t)k * DDIM);
    float s = 0.f;
    #pragma unroll 4
    for (int d4 = 0; d4 < DDIM / 4; d4++) {
        float4 v = row4[d4];
        s = __fmaf_rn(v.x, v.x, s);   // sequential chain (matched JAX in R1/R2/R5)
        s = __fmaf_rn(v.y, v.y, s);
        s = __fmaf_rn(v.z, v.z, s);
        s = __fmaf_rn(v.w, v.w, s);
        out[d4 * 2 + 0] = cvt_bf16x2(v.x, v.y);
        out[d4 * 2 + 1] = cvt_bf16x2(v.z, v.w);
    }
    g_cnorm[k] = s;
}

// ---------------- (2) znorm (exact chain) + g_minu init ----------------
__global__ void znorm_init_kernel(const float* __restrict__ z) {
    int n = blockIdx.x * blockDim.x + threadIdx.x;
    if (n >= N_ROWS) return;
    int b = n >> 10, p = n & 1023;
    const float* zp = z + (size_t)b * DDIM * HW + p;
    float s = 0.f;
    #pragma unroll 8
    for (int d = 0; d < DDIM; d++) { float v = zp[(size_t)d * HW]; s = __fmaf_rn(v, v, s); }
    g_znorm[n] = s;
    g_minu[n] = 0xFFFFFFFFu;
}

// ---------------- (3) transpose z -> token-major fp32 + bf16 ----------------
__global__ void transpose_kernel(const float* __restrict__ z) {
    __shared__ float ts[32][33];
    int t = threadIdx.x, tx = t & 31, ty = t >> 5;   // 32 x 8
    int pt = blockIdx.x & 31, dt = blockIdx.x >> 5;  // 32 p-tiles, 8 d-tiles
    int b  = blockIdx.y;
    int p0 = pt * 32, d0 = dt * 32;
    #pragma unroll
    for (int i = 0; i < 4; i++) {
        int d = d0 + ty + i * 8;
        ts[ty + i * 8][tx] = z[((size_t)(b * DDIM + d)) * HW + p0 + tx];
    }
    __syncthreads();
    #pragma unroll
    for (int i = 0; i < 4; i++) {
        int n = b * HW + p0 + ty + i * 8;
        float v = ts[tx][ty + i * 8];
        g_zt [(size_t)n * DDIM + d0 + tx] = v;
        g_ztb[(size_t)n * DDIM + d0 + tx] = __float2bfloat16(v);
    }
}

// ---------------- (4) coarse GEMM + fused coarse-min epilogue ---------------
// CTA: 128 tokens x 128 codes, 8 warps 4(m)x2(n), warp tile 32x64.
// K=256 in 4 chunks of 64; ldmatrix.x4 fragment loads (conflict-free, PITCH=72).
#define PITCH 72

__global__ void __launch_bounds__(256, 2) mma_kernel() {
    __shared__ __align__(16) __nv_bfloat16 As[128 * PITCH];
    __shared__ __align__(16) __nv_bfloat16 Bs[128 * PITCH];

    const int t = threadIdx.x, wid = t >> 5, lane = t & 31;
    const int row0 = blockIdx.x * 128, col0 = blockIdx.y * 128;
    const int wm = (wid & 3) * 32;        // warp m-offset
    const int wn = (wid >> 2) * 64;       // warp n-offset
    const int r  = lane >> 2, tt = lane & 3;
    const int grp = lane >> 3, l7 = lane & 7;

    // ldmatrix lane base addresses.
    // A: matrices {(m,k),(m+8,k),(m,k+8),(m+8,k+8)} -> regs a0..a3
    const int a_row = (grp & 1) * 8 + l7, a_k = (grp & 2) * 4;
    // B: matrices {(n,k),(n,k+8),(n+8,k),(n+8,k+8)} -> b0,b1 of nt / nt+1
    const int b_row = (grp & 2) * 4 + l7, b_k = (grp & 1) * 8;
    const uint32_t asb = smem_u32(As), bsb = smem_u32(Bs);
    uint32_t aAddr[2], bAddr[4];
    #pragma unroll
    for (int mt = 0; mt < 2; mt++)
        aAddr[mt] = asb + ((wm + mt * 16 + a_row) * PITCH + a_k) * 2;
    #pragma unroll
    for (int p = 0; p < 4; p++)
        bAddr[p] = bsb + ((wn + p * 16 + b_row) * PITCH + b_k) * 2;

    float acc[2][8][4];
    #pragma unroll
    for (int mt = 0; mt < 2; mt++)
        #pragma unroll
        for (int nt = 0; nt < 8; nt++)
            #pragma unroll
            for (int q = 0; q < 4; q++) acc[mt][nt][q] = 0.f;

    for (int ch = 0; ch < 4; ch++) {
        const int cd0 = ch * 64;
        #pragma unroll
        for (int it = 0; it < 4; it++) {
            int idx = it * 256 + t;            // 0..1023
            int rr = idx >> 3, k8 = (idx & 7) * 8;
            *reinterpret_cast<uint4*>(&As[rr * PITCH + k8]) =
                *reinterpret_cast<const uint4*>(&g_ztb[(size_t)(row0 + rr) * DDIM + cd0 + k8]);
            *reinterpret_cast<uint4*>(&Bs[rr * PITCH + k8]) =
                *reinterpret_cast<const uint4*>(&g_cbb[(size_t)(col0 + rr) * DDIM + cd0 + k8]);
        }
        __syncthreads();

        #pragma unroll
        for (int ks = 0; ks < 4; ks++) {
            const uint32_t koff = ks * 32;     // 16 halves
            uint32_t A0[4], A1[4];
            ldsm4(A0[0], A0[1], A0[2], A0[3], aAddr[0] + koff);
            ldsm4(A1[0], A1[1], A1[2], A1[3], aAddr[1] + koff);
            #pragma unroll
            for (int p = 0; p < 4; p++) {
                uint32_t B[4];
                ldsm4(B[0], B[1], B[2], B[3], bAddr[p] + koff);
                mma16816(acc[0][2 * p],     A0[0], A0[1], A0[2], A0[3], B[0], B[1]);
                mma16816(acc[0][2 * p + 1], A0[0], A0[1], A0[2], A0[3], B[2], B[3]);
                mma16816(acc[1][2 * p],     A1[0], A1[1], A1[2], A1[3], B[0], B[1]);
                mma16816(acc[1][2 * p + 1], A1[0], A1[1], A1[2], A1[3], B[2], B[3]);
            }
        }
        __syncthreads();
    }

    // epilogue: coarse = cnorm - 2*dot; store bf16 pairs; fused per-row min.
    #pragma unroll
    for (int mt = 0; mt < 2; mt++) {
        const int grow = row0 + wm + mt * 16 + r;
        float rmin0 = 3.4e38f, rmin8 = 3.4e38f;
        #pragma unroll
        for (int nt = 0; nt < 8; nt++) {
            const int cbase = col0 + wn + nt * 8;
            float2 cn = *reinterpret_cast<const float2*>(&g_cnorm[cbase + tt * 2]);
            float d0 = __fmaf_rn(-2.f, acc[mt][nt][0], cn.x);
            float d1 = __fmaf_rn(-2.f, acc[mt][nt][1], cn.y);
            float d2 = __fmaf_rn(-2.f, acc[mt][nt][2], cn.x);
            float d3 = __fmaf_rn(-2.f, acc[mt][nt][3], cn.y);
            g_S[(size_t)grow * (KCODES / 2) + (cbase >> 1) + tt]       = cvt_bf16x2(d0, d1);
            g_S[(size_t)(grow + 8) * (KCODES / 2) + (cbase >> 1) + tt] = cvt_bf16x2(d2, d3);
            rmin0 = fminf(rmin0, fminf(d0, d1));
            rmin8 = fminf(rmin8, fminf(d2, d3));
        }
        #pragma unroll
        for (int off = 1; off < 4; off <<= 1) {
            rmin0 = fminf(rmin0, __shfl_xor_sync(0xffffffffu, rmin0, off));
            rmin8 = fminf(rmin8, __shfl_xor_sync(0xffffffffu, rmin8, off));
        }
        if (tt == 0) {
            atomicMin(&g_minu[grow],     fmap(rmin0));
            atomicMin(&g_minu[grow + 8], fmap(rmin8));
        }
    }
}

// ---------------- (5) scan: threshold from g_minu + exact fp32 rescore ------
#define MARGIN 8e-3f

__global__ void __launch_bounds__(256) scan_kernel(const float* __restrict__ cb) {
    int n = (blockIdx.x * blockDim.x + threadIdx.x) >> 5;   // warp per token
    int lane = threadIdx.x & 31;
    const uint32_t* srow = g_S + (size_t)n * (KCODES / 2);
    const float zn = g_znorm[n];
    const float thresh = funmap(g_minu[n]) + MARGIN;

    unsigned long long best = 0xffffffffffffffffull;
    for (int it = 0; it < 32; it++) {
        int j = it * 32 + lane;
        uint32_t v = srow[j];
        __nv_bfloat162 bb = *reinterpret_cast<__nv_bfloat162*>(&v);
        #pragma unroll
        for (int h = 0; h < 2; h++) {
            float cv = h ? __bfloat162float(bb.y) : __bfloat162float(bb.x);
            if (cv <= thresh) {
                int k = 2 * j + h;
                const float4* za4 = reinterpret_cast<const float4*>(g_zt + (size_t)n * DDIM);
                const float4* ca4 = reinterpret_cast<const float4*>(cb + (size_t)k * DDIM);
                float acc = 0.f;
                #pragma unroll 8
                for (int d4 = 0; d4 < DDIM / 4; d4++) {
                    float4 a = za4[d4], c = ca4[d4];
                    acc = __fmaf_rn(a.x, c.x, acc);   // identical sequential chain
                    acc = __fmaf_rn(a.y, c.y, acc);
                    acc = __fmaf_rn(a.z, c.z, acc);
                    acc = __fmaf_rn(a.w, c.w, acc);
                }
                float dist = __fadd_rn(__fadd_rn(zn, g_cnorm[k]), -2.0f * acc);
                unsigned long long pk =
                    ((unsigned long long)__float_as_uint(dist) << 32) | (unsigned)k;
                if (pk < best) best = pk;
            }
        }
    }
    #pragma unroll
    for (int off = 16; off; off >>= 1) {
        unsigned long long o = __shfl_xor_sync(0xffffffffu, best, off);
        if (o < best) best = o;
    }
    if (lane == 0) g_bestIdx[n] = (int)(best & 0xffffffffu);
}

// ---------------- (6) gather + STE (unchanged, matched 3x) ----------------
__global__ void gather_kernel(const float* __restrict__ z,
                              const float* __restrict__ cb,
                              float* __restrict__ out) {
    int o4 = blockIdx.x * blockDim.x + threadIdx.x;
    int p4 = o4 & 255, d = (o4 >> 8) & 255, b = o4 >> 16;
    int p = p4 * 4, nb = b * HW + p;
    size_t off = ((size_t)(b * DDIM + d)) * HW + p;
    float4 zv = *reinterpret_cast<const float4*>(z + off);
    float q0 = cb[(size_t)g_bestIdx[nb + 0] * DDIM + d];
    float q1 = cb[(size_t)g_bestIdx[nb + 1] * DDIM + d];
    float q2 = cb[(size_t)g_bestIdx[nb + 2] * DDIM + d];
    float q3 = cb[(size_t)g_bestIdx[nb + 3] * DDIM + d];
    float4 r;
    r.x = __fadd_rn(zv.x, __fadd_rn(q0, -zv.x));
    r.y = __fadd_rn(zv.y, __fadd_rn(q1, -zv.y));
    r.z = __fadd_rn(zv.z, __fadd_rn(q2, -zv.z));
    r.w = __fadd_rn(zv.w, __fadd_rn(q3, -zv.w));
    *reinterpret_cast<float4*>(out + off) = r;
}

// ---------------------------------------------------------------------------
// Launch order puts mma_kernel 4th: the ncu capture empirically profiles the
// 4th launch (R1/R2 gather, R5 znorm were all 4th) — we need tensor-pipe data.
extern "C" void kernel_launch(void* const* d_in, const int* in_sizes, int n_in,
                              void* d_out, int out_size) {
    const float* z  = (const float*)d_in[0];
    const float* cb = (const float*)d_in[1];
    float* out = (float*)d_out;

    cbcnorm_kernel<<<KCODES / 256, 256>>>(cb);              // 1
    znorm_init_kernel<<<N_ROWS / 256, 256>>>(z);            // 2
    transpose_kernel<<<dim3(256, 16), 256>>>(z);            // 3
    mma_kernel<<<dim3(N_ROWS / 128, KCODES / 128), 256>>>();// 4  <- profiled
    scan_kernel<<<(N_ROWS * 32) / 256, 256>>>(cb);          // 5
    gather_kernel<<<(N_ROWS * DDIM / 4) / 256, 256>>>(z, cb, out); // 6
}

// round 7
// speedup vs baseline: 3.9827x; 3.2295x over previous
#include <cuda_runtime.h>
#include <cuda_bf16.h>
#include <cstdint>

// Shapes (fixed): z (16,256,32,32) fp32; codebook (2048,256) fp32; out like z.
#define N_ROWS 16384
#define DDIM   256
#define KCODES 2048
#define HW     1024
#define CAND_CAP (1 << 18)   // 262144 candidate slots (expect ~30-50K)

// ---------------- device scratch (no mallocs allowed) ----------------
__device__ float              g_cnorm[KCODES];
__device__ float              g_znorm[N_ROWS];
__device__ uint32_t           g_minu[N_ROWS];          // monotonic-mapped coarse row min
__device__ unsigned long long g_best[N_ROWS];          // packed (dist_bits<<32)|idx
__device__ int                g_candCount;
__device__ uint32_t           g_cand[CAND_CAP];        // packed n<<11 | k
__device__ float              g_zt [N_ROWS * DDIM];    // token-major fp32 z
__device__ __nv_bfloat16      g_ztb[N_ROWS * DDIM];    // token-major bf16 z
__device__ __nv_bfloat16      g_cbb[KCODES * DDIM];    // bf16 codebook
__device__ uint32_t           g_S  [N_ROWS * KCODES / 2]; // coarse dists, bf16 pairs

// ---------------- small helpers ----------------
__device__ __forceinline__ uint32_t cvt_bf16x2(float a, float b) {  // lo=a, hi=b
    uint32_t r;
    asm("cvt.rn.bf16x2.f32 %0, %1, %2;" : "=r"(r) : "f"(b), "f"(a));
    return r;
}
__device__ __forceinline__ uint32_t fmap(float f) {   // order-preserving f32->u32
    uint32_t b = __float_as_uint(f);
    return (b & 0x80000000u) ? ~b : (b | 0x80000000u);
}
__device__ __forceinline__ float funmap(uint32_t u) {
    uint32_t b = (u & 0x80000000u) ? (u & 0x7fffffffu) : ~u;
    return __uint_as_float(b);
}
__device__ __forceinline__ void ldsm4(uint32_t& r0, uint32_t& r1, uint32_t& r2,
                                      uint32_t& r3, uint32_t addr) {
    asm volatile("ldmatrix.sync.aligned.m8n8.x4.shared.b16 {%0,%1,%2,%3}, [%4];"
                 : "=r"(r0), "=r"(r1), "=r"(r2), "=r"(r3) : "r"(addr));
}
__device__ __forceinline__ uint32_t smem_u32(const void* p) {
    uint32_t a;
    asm("{ .reg .u64 t; cvta.to.shared.u64 t, %1; cvt.u32.u64 %0, t; }" : "=r"(a) : "l"(p));
    return a;
}
__device__ __forceinline__ void mma16816(float* c, uint32_t a0, uint32_t a1,
                                         uint32_t a2, uint32_t a3,
                                         uint32_t b0, uint32_t b1) {
    asm volatile(
        "mma.sync.aligned.m16n8k16.row.col.f32.bf16.bf16.f32 "
        "{%0,%1,%2,%3}, {%4,%5,%6,%7}, {%8,%9}, {%0,%1,%2,%3};"
        : "+f"(c[0]), "+f"(c[1]), "+f"(c[2]), "+f"(c[3])
        : "r"(a0), "r"(a1), "r"(a2), "r"(a3), "r"(b0), "r"(b1));
}

// ---------------- (1) codebook: bf16 convert + exact sequential cnorm -------
__global__ void cbcnorm_kernel(const float* __restrict__ cb) {
    int k = blockIdx.x * blockDim.x + threadIdx.x;
    if (k >= KCODES) return;
    const float4* row4 = reinterpret_cast<const float4*>(cb + (size_t)k * DDIM);
    uint32_t* out = reinterpret_cast<uint32_t*>(g_cbb + (size_t)k * DDIM);
    float s = 0.f;
    #pragma unroll 4
    for (int d4 = 0; d4 < DDIM / 4; d4++) {
        float4 v = row4[d4];
        s = __fmaf_rn(v.x, v.x, s);   // sequential chain (matched JAX 4x)
        s = __fmaf_rn(v.y, v.y, s);
        s = __fmaf_rn(v.z, v.z, s);
        s = __fmaf_rn(v.w, v.w, s);
        out[d4 * 2 + 0] = cvt_bf16x2(v.x, v.y);
        out[d4 * 2 + 1] = cvt_bf16x2(v.z, v.w);
    }
    g_cnorm[k] = s;
}

// ---------------- (2) znorm (exact chain) + state init ----------------
__global__ void znorm_init_kernel(const float* __restrict__ z) {
    int n = blockIdx.x * blockDim.x + threadIdx.x;
    if (n >= N_ROWS) return;
    int b = n >> 10, p = n & 1023;
    const float* zp = z + (size_t)b * DDIM * HW + p;
    float s = 0.f;
    #pragma unroll 8
    for (int d = 0; d < DDIM; d++) { float v = zp[(size_t)d * HW]; s = __fmaf_rn(v, v, s); }
    g_znorm[n] = s;
    g_minu[n] = 0xFFFFFFFFu;
    g_best[n] = 0xFFFFFFFFFFFFFFFFull;
    if (n == 0) g_candCount = 0;
}

// ---------------- (3) transpose z -> token-major fp32 + bf16 ----------------
__global__ void transpose_kernel(const float* __restrict__ z) {
    __shared__ float ts[32][33];
    int t = threadIdx.x, tx = t & 31, ty = t >> 5;   // 32 x 8
    int pt = blockIdx.x & 31, dt = blockIdx.x >> 5;
    int b  = blockIdx.y;
    int p0 = pt * 32, d0 = dt * 32;
    #pragma unroll
    for (int i = 0; i < 4; i++) {
        int d = d0 + ty + i * 8;
        ts[ty + i * 8][tx] = z[((size_t)(b * DDIM + d)) * HW + p0 + tx];
    }
    __syncthreads();
    #pragma unroll
    for (int i = 0; i < 4; i++) {
        int n = b * HW + p0 + ty + i * 8;
        float v = ts[tx][ty + i * 8];
        g_zt [(size_t)n * DDIM + d0 + tx] = v;
        g_ztb[(size_t)n * DDIM + d0 + tx] = __float2bfloat16(v);
    }
}

// ---------------- (4) coarse GEMM + fused coarse-min epilogue (as R6) -------
#define PITCH 72

__global__ void __launch_bounds__(256, 2) mma_kernel() {
    __shared__ __align__(16) __nv_bfloat16 As[128 * PITCH];
    __shared__ __align__(16) __nv_bfloat16 Bs[128 * PITCH];

    const int t = threadIdx.x, wid = t >> 5, lane = t & 31;
    const int row0 = blockIdx.x * 128, col0 = blockIdx.y * 128;
    const int wm = (wid & 3) * 32;
    const int wn = (wid >> 2) * 64;
    const int r  = lane >> 2, tt = lane & 3;
    const int grp = lane >> 3, l7 = lane & 7;

    const int a_row = (grp & 1) * 8 + l7, a_k = (grp & 2) * 4;
    const int b_row = (grp & 2) * 4 + l7, b_k = (grp & 1) * 8;
    const uint32_t asb = smem_u32(As), bsb = smem_u32(Bs);
    uint32_t aAddr[2], bAddr[4];
    #pragma unroll
    for (int mt = 0; mt < 2; mt++)
        aAddr[mt] = asb + ((wm + mt * 16 + a_row) * PITCH + a_k) * 2;
    #pragma unroll
    for (int p = 0; p < 4; p++)
        bAddr[p] = bsb + ((wn + p * 16 + b_row) * PITCH + b_k) * 2;

    float acc[2][8][4];
    #pragma unroll
    for (int mt = 0; mt < 2; mt++)
        #pragma unroll
        for (int nt = 0; nt < 8; nt++)
            #pragma unroll
            for (int q = 0; q < 4; q++) acc[mt][nt][q] = 0.f;

    for (int ch = 0; ch < 4; ch++) {
        const int cd0 = ch * 64;
        #pragma unroll
        for (int it = 0; it < 4; it++) {
            int idx = it * 256 + t;
            int rr = idx >> 3, k8 = (idx & 7) * 8;
            *reinterpret_cast<uint4*>(&As[rr * PITCH + k8]) =
                *reinterpret_cast<const uint4*>(&g_ztb[(size_t)(row0 + rr) * DDIM + cd0 + k8]);
            *reinterpret_cast<uint4*>(&Bs[rr * PITCH + k8]) =
                *reinterpret_cast<const uint4*>(&g_cbb[(size_t)(col0 + rr) * DDIM + cd0 + k8]);
        }
        __syncthreads();

        #pragma unroll
        for (int ks = 0; ks < 4; ks++) {
            const uint32_t koff = ks * 32;
            uint32_t A0[4], A1[4];
            ldsm4(A0[0], A0[1], A0[2], A0[3], aAddr[0] + koff);
            ldsm4(A1[0], A1[1], A1[2], A1[3], aAddr[1] + koff);
            #pragma unroll
            for (int p = 0; p < 4; p++) {
                uint32_t B[4];
                ldsm4(B[0], B[1], B[2], B[3], bAddr[p] + koff);
                mma16816(acc[0][2 * p],     A0[0], A0[1], A0[2], A0[3], B[0], B[1]);
                mma16816(acc[0][2 * p + 1], A0[0], A0[1], A0[2], A0[3], B[2], B[3]);
                mma16816(acc[1][2 * p],     A1[0], A1[1], A1[2], A1[3], B[0], B[1]);
                mma16816(acc[1][2 * p + 1], A1[0], A1[1], A1[2], A1[3], B[2], B[3]);
            }
        }
        __syncthreads();
    }

    #pragma unroll
    for (int mt = 0; mt < 2; mt++) {
        const int grow = row0 + wm + mt * 16 + r;
        float rmin0 = 3.4e38f, rmin8 = 3.4e38f;
        #pragma unroll
        for (int nt = 0; nt < 8; nt++) {
            const int cbase = col0 + wn + nt * 8;
            float2 cn = *reinterpret_cast<const float2*>(&g_cnorm[cbase + tt * 2]);
            float d0 = __fmaf_rn(-2.f, acc[mt][nt][0], cn.x);
            float d1 = __fmaf_rn(-2.f, acc[mt][nt][1], cn.y);
            float d2 = __fmaf_rn(-2.f, acc[mt][nt][2], cn.x);
            float d3 = __fmaf_rn(-2.f, acc[mt][nt][3], cn.y);
            g_S[(size_t)grow * (KCODES / 2) + (cbase >> 1) + tt]       = cvt_bf16x2(d0, d1);
            g_S[(size_t)(grow + 8) * (KCODES / 2) + (cbase >> 1) + tt] = cvt_bf16x2(d2, d3);
            rmin0 = fminf(rmin0, fminf(d0, d1));
            rmin8 = fminf(rmin8, fminf(d2, d3));
        }
        #pragma unroll
        for (int off = 1; off < 4; off <<= 1) {
            rmin0 = fminf(rmin0, __shfl_xor_sync(0xffffffffu, rmin0, off));
            rmin8 = fminf(rmin8, __shfl_xor_sync(0xffffffffu, rmin8, off));
        }
        if (tt == 0) {
            atomicMin(&g_minu[grow],     fmap(rmin0));
            atomicMin(&g_minu[grow + 8], fmap(rmin8));
        }
    }
}

// ---------------- (5) filter: stream S (L2-hot), append candidates ----------
// Worst-case bound: coarse err <= 4e-4 (bf16 dot) + 8e-5 (bf16 store) + grid
// rounding 6e-5 -> need ~1.1e-3. 2.5e-3 = 2.3x slack.
#define MARGIN 2.5e-3f

__global__ void __launch_bounds__(256) filter_kernel() {
    const int n = blockIdx.x;                 // one token row per CTA
    const int t = threadIdx.x;
    const float thresh = funmap(g_minu[n]) + MARGIN;
    uint4 v = reinterpret_cast<const uint4*>(g_S + (size_t)n * (KCODES / 2))[t];
    const int kbase = t * 8;                  // 8 codes per thread
    uint32_t ws[4] = {v.x, v.y, v.z, v.w};
    #pragma unroll
    for (int q = 0; q < 4; q++) {
        __nv_bfloat162 bb = *reinterpret_cast<__nv_bfloat162*>(&ws[q]);
        float c0 = __bfloat162float(bb.x), c1 = __bfloat162float(bb.y);
        if (c0 <= thresh) {
            int pos = atomicAdd(&g_candCount, 1);
            if (pos < CAND_CAP) g_cand[pos] = ((uint32_t)n << 11) | (kbase + 2 * q);
        }
        if (c1 <= thresh) {
            int pos = atomicAdd(&g_candCount, 1);
            if (pos < CAND_CAP) g_cand[pos] = ((uint32_t)n << 11) | (kbase + 2 * q + 1);
        }
    }
}

// ---------------- (6) rescore: one thread per candidate, exact chain --------
__global__ void __launch_bounds__(256) rescore_kernel(const float* __restrict__ cb) {
    int i = blockIdx.x * blockDim.x + threadIdx.x;
    int cnt = g_candCount;
    if (cnt > CAND_CAP) cnt = CAND_CAP;
    if (i >= cnt) return;
    uint32_t e = g_cand[i];
    int n = e >> 11, k = e & 2047;
    const float4* za4 = reinterpret_cast<const float4*>(g_zt + (size_t)n * DDIM);
    const float4* ca4 = reinterpret_cast<const float4*>(cb + (size_t)k * DDIM);
    float acc = 0.f;
    #pragma unroll 8
    for (int d4 = 0; d4 < DDIM / 4; d4++) {
        float4 a = za4[d4], c = ca4[d4];
        acc = __fmaf_rn(a.x, c.x, acc);   // identical sequential chain (4x verified)
        acc = __fmaf_rn(a.y, c.y, acc);
        acc = __fmaf_rn(a.z, c.z, acc);
        acc = __fmaf_rn(a.w, c.w, acc);
    }
    float dist = __fadd_rn(__fadd_rn(g_znorm[n], g_cnorm[k]), -2.0f * acc);
    // dist > 0 always (~256), so float bits are order-preserving; ties -> lowest k
    unsigned long long pk = ((unsigned long long)__float_as_uint(dist) << 32) | (unsigned)k;
    atomicMin(&g_best[n], pk);
}

// ---------------- (7) gather + STE (chain matched 4x) ----------------
__global__ void gather_kernel(const float* __restrict__ z,
                              const float* __restrict__ cb,
                              float* __restrict__ out) {
    int o4 = blockIdx.x * blockDim.x + threadIdx.x;
    int p4 = o4 & 255, d = (o4 >> 8) & 255, b = o4 >> 16;
    int p = p4 * 4, nb = b * HW + p;
    size_t off = ((size_t)(b * DDIM + d)) * HW + p;
    float4 zv = *reinterpret_cast<const float4*>(z + off);
    int k0 = (int)(g_best[nb + 0] & 0xffffffffu);
    int k1 = (int)(g_best[nb + 1] & 0xffffffffu);
    int k2 = (int)(g_best[nb + 2] & 0xffffffffu);
    int k3 = (int)(g_best[nb + 3] & 0xffffffffu);
    float q0 = cb[(size_t)k0 * DDIM + d];
    float q1 = cb[(size_t)k1 * DDIM + d];
    float q2 = cb[(size_t)k2 * DDIM + d];
    float q3 = cb[(size_t)k3 * DDIM + d];
    float4 r;
    r.x = __fadd_rn(zv.x, __fadd_rn(q0, -zv.x));
    r.y = __fadd_rn(zv.y, __fadd_rn(q1, -zv.y));
    r.z = __fadd_rn(zv.z, __fadd_rn(q2, -zv.z));
    r.w = __fadd_rn(zv.w, __fadd_rn(q3, -zv.w));
    *reinterpret_cast<float4*>(out + off) = r;
}

// ---------------------------------------------------------------------------
// mma stays launch #4 (profiler slot).
extern "C" void kernel_launch(void* const* d_in, const int* in_sizes, int n_in,
                              void* d_out, int out_size) {
    const float* z  = (const float*)d_in[0];
    const float* cb = (const float*)d_in[1];
    float* out = (float*)d_out;

    cbcnorm_kernel<<<KCODES / 256, 256>>>(cb);               // 1
    znorm_init_kernel<<<N_ROWS / 256, 256>>>(z);             // 2
    transpose_kernel<<<dim3(256, 16), 256>>>(z);             // 3
    mma_kernel<<<dim3(N_ROWS / 128, KCODES / 128), 256>>>(); // 4 <- profiled
    filter_kernel<<<N_ROWS, 256>>>();                        // 5
    rescore_kernel<<<CAND_CAP / 256, 256>>>(cb);             // 6
    gather_kernel<<<(N_ROWS * DDIM / 4) / 256, 256>>>(z, cb, out); // 7
}

// round 8
// speedup vs baseline: 4.5181x; 1.1344x over previous
#include <cuda_runtime.h>
#include <cuda_bf16.h>
#include <cstdint>

// Shapes (fixed): z (16,256,32,32) fp32; codebook (2048,256) fp32; out like z.
#define N_ROWS 16384
#define DDIM   256
#define KCODES 2048
#define HW     1024
#define CAND_CAP (1 << 22)   // 4M coarse candidates (est ~840K -> 5x slack)
#define RESC_CAP (1 << 19)   // 512K survivors (est ~50K)

// Margin: worst-case coarse error 2*(bf16 dot err 4e-4) + bf16 store 8e-5
// + output grid rounding ~6e-5 => need ~9e-4. 2.5e-3 validated in R7.
#define MARGIN 2.5e-3f

// ---------------- device scratch (no mallocs allowed) ----------------
__device__ float              g_cnorm[KCODES];
__device__ uint32_t           g_minu[N_ROWS];          // monotonic-mapped coarse row min
__device__ unsigned long long g_best[N_ROWS];          // packed (dist_bits<<32)|idx
__device__ int                g_candCount;
__device__ int                g_rescCount;
__device__ unsigned long long g_cand[CAND_CAP];        // (coarse_bf16<<32)|(n<<11)|k
__device__ uint32_t           g_resc[RESC_CAP];        // (n<<11)|k survivors
__device__ float              g_zt [N_ROWS * DDIM];    // token-major fp32 z
__device__ __nv_bfloat16      g_ztb[N_ROWS * DDIM];    // token-major bf16 z
__device__ __nv_bfloat16      g_cbb[KCODES * DDIM];    // bf16 codebook

// ---------------- small helpers ----------------
__device__ __forceinline__ uint32_t cvt_bf16x2(float a, float b) {  // lo=a, hi=b
    uint32_t r;
    asm("cvt.rn.bf16x2.f32 %0, %1, %2;" : "=r"(r) : "f"(b), "f"(a));
    return r;
}
__device__ __forceinline__ uint32_t fmap(float f) {   // order-preserving f32->u32
    uint32_t b = __float_as_uint(f);
    return (b & 0x80000000u) ? ~b : (b | 0x80000000u);
}
__device__ __forceinline__ float funmap(uint32_t u) {
    uint32_t b = (u & 0x80000000u) ? (u & 0x7fffffffu) : ~u;
    return __uint_as_float(b);
}
__device__ __forceinline__ void ldsm4(uint32_t& r0, uint32_t& r1, uint32_t& r2,
                                      uint32_t& r3, uint32_t addr) {
    asm volatile("ldmatrix.sync.aligned.m8n8.x4.shared.b16 {%0,%1,%2,%3}, [%4];"
                 : "=r"(r0), "=r"(r1), "=r"(r2), "=r"(r3) : "r"(addr));
}
__device__ __forceinline__ uint32_t smem_u32(const void* p) {
    uint32_t a;
    asm("{ .reg .u64 t; cvta.to.shared.u64 t, %1; cvt.u32.u64 %0, t; }" : "=r"(a) : "l"(p));
    return a;
}
__device__ __forceinline__ void mma16816(float* c, uint32_t a0, uint32_t a1,
                                         uint32_t a2, uint32_t a3,
                                         uint32_t b0, uint32_t b1) {
    asm volatile(
        "mma.sync.aligned.m16n8k16.row.col.f32.bf16.bf16.f32 "
        "{%0,%1,%2,%3}, {%4,%5,%6,%7}, {%8,%9}, {%0,%1,%2,%3};"
        : "+f"(c[0]), "+f"(c[1]), "+f"(c[2]), "+f"(c[3])
        : "r"(a0), "r"(a1), "r"(a2), "r"(a3), "r"(b0), "r"(b1));
}

// ---------------- (1) init per-replay state (no z read) ----------------
__global__ void init_kernel() {
    int n = blockIdx.x * blockDim.x + threadIdx.x;
    if (n >= N_ROWS) return;
    g_minu[n] = 0xFFFFFFFFu;
    g_best[n] = 0xFFFFFFFFFFFFFFFFull;
    if (n == 0) { g_candCount = 0; g_rescCount = 0; }
}

// ---------------- (2) codebook: bf16 convert + exact sequential cnorm -------
__global__ void cbcnorm_kernel(const float* __restrict__ cb) {
    int k = blockIdx.x * blockDim.x + threadIdx.x;
    if (k >= KCODES) return;
    const float4* row4 = reinterpret_cast<const float4*>(cb + (size_t)k * DDIM);
    uint32_t* out = reinterpret_cast<uint32_t*>(g_cbb + (size_t)k * DDIM);
    float s = 0.f;
    #pragma unroll 4
    for (int d4 = 0; d4 < DDIM / 4; d4++) {
        float4 v = row4[d4];
        s = __fmaf_rn(v.x, v.x, s);   // sequential chain (matched JAX 5x)
        s = __fmaf_rn(v.y, v.y, s);
        s = __fmaf_rn(v.z, v.z, s);
        s = __fmaf_rn(v.w, v.w, s);
        out[d4 * 2 + 0] = cvt_bf16x2(v.x, v.y);
        out[d4 * 2 + 1] = cvt_bf16x2(v.z, v.w);
    }
    g_cnorm[k] = s;
}

// ---------------- (3) transpose z -> token-major fp32 + bf16 ----------------
__global__ void transpose_kernel(const float* __restrict__ z) {
    __shared__ float ts[32][33];
    int t = threadIdx.x, tx = t & 31, ty = t >> 5;   // 32 x 8
    int pt = blockIdx.x & 31, dt = blockIdx.x >> 5;
    int b  = blockIdx.y;
    int p0 = pt * 32, d0 = dt * 32;
    #pragma unroll
    for (int i = 0; i < 4; i++) {
        int d = d0 + ty + i * 8;
        ts[ty + i * 8][tx] = z[((size_t)(b * DDIM + d)) * HW + p0 + tx];
    }
    __syncthreads();
    #pragma unroll
    for (int i = 0; i < 4; i++) {
        int n = b * HW + p0 + ty + i * 8;
        float v = ts[tx][ty + i * 8];
        g_zt [(size_t)n * DDIM + d0 + tx] = v;
        g_ztb[(size_t)n * DDIM + d0 + tx] = __float2bfloat16(v);
    }
}

// ---------------- (4) coarse GEMM + fused min + candidate emission ----------
// Mainloop identical to R6/R7 (verified). Epilogue: no S store; emit
// (coarse_bf16, n, k) for codes within warp-local min + margin.
#define PITCH 72

__global__ void __launch_bounds__(256, 2) mma_kernel() {
    __shared__ __align__(16) __nv_bfloat16 As[128 * PITCH];
    __shared__ __align__(16) __nv_bfloat16 Bs[128 * PITCH];
    __shared__ int s_cnt, s_base;

    const int t = threadIdx.x, wid = t >> 5, lane = t & 31;
    const int row0 = blockIdx.x * 128, col0 = blockIdx.y * 128;
    const int wm = (wid & 3) * 32;
    const int wn = (wid >> 2) * 64;
    const int r  = lane >> 2, tt = lane & 3;
    const int grp = lane >> 3, l7 = lane & 7;

    const int a_row = (grp & 1) * 8 + l7, a_k = (grp & 2) * 4;
    const int b_row = (grp & 2) * 4 + l7, b_k = (grp & 1) * 8;
    const uint32_t asb = smem_u32(As), bsb = smem_u32(Bs);
    uint32_t aAddr[2], bAddr[4];
    #pragma unroll
    for (int mt = 0; mt < 2; mt++)
        aAddr[mt] = asb + ((wm + mt * 16 + a_row) * PITCH + a_k) * 2;
    #pragma unroll
    for (int p = 0; p < 4; p++)
        bAddr[p] = bsb + ((wn + p * 16 + b_row) * PITCH + b_k) * 2;

    float acc[2][8][4];
    #pragma unroll
    for (int mt = 0; mt < 2; mt++)
        #pragma unroll
        for (int nt = 0; nt < 8; nt++)
            #pragma unroll
            for (int q = 0; q < 4; q++) acc[mt][nt][q] = 0.f;

    for (int ch = 0; ch < 4; ch++) {
        const int cd0 = ch * 64;
        #pragma unroll
        for (int it = 0; it < 4; it++) {
            int idx = it * 256 + t;
            int rr = idx >> 3, k8 = (idx & 7) * 8;
            *reinterpret_cast<uint4*>(&As[rr * PITCH + k8]) =
                *reinterpret_cast<const uint4*>(&g_ztb[(size_t)(row0 + rr) * DDIM + cd0 + k8]);
            *reinterpret_cast<uint4*>(&Bs[rr * PITCH + k8]) =
                *reinterpret_cast<const uint4*>(&g_cbb[(size_t)(col0 + rr) * DDIM + cd0 + k8]);
        }
        __syncthreads();

        #pragma unroll
        for (int ks = 0; ks < 4; ks++) {
            const uint32_t koff = ks * 32;
            uint32_t A0[4], A1[4];
            ldsm4(A0[0], A0[1], A0[2], A0[3], aAddr[0] + koff);
            ldsm4(A1[0], A1[1], A1[2], A1[3], aAddr[1] + koff);
            #pragma unroll
            for (int p = 0; p < 4; p++) {
                uint32_t B[4];
                ldsm4(B[0], B[1], B[2], B[3], bAddr[p] + koff);
                mma16816(acc[0][2 * p],     A0[0], A0[1], A0[2], A0[3], B[0], B[1]);
                mma16816(acc[0][2 * p + 1], A0[0], A0[1], A0[2], A0[3], B[2], B[3]);
                mma16816(acc[1][2 * p],     A1[0], A1[1], A1[2], A1[3], B[0], B[1]);
                mma16816(acc[1][2 * p + 1], A1[0], A1[1], A1[2], A1[3], B[2], B[3]);
            }
        }
        __syncthreads();
    }

    // --- epilogue: overwrite acc with coarse = cnorm - 2*dot, track row mins
    float rmin[2][2];
    #pragma unroll
    for (int mt = 0; mt < 2; mt++) { rmin[mt][0] = 3.4e38f; rmin[mt][1] = 3.4e38f; }
    #pragma unroll
    for (int mt = 0; mt < 2; mt++)
        #pragma unroll
        for (int nt = 0; nt < 8; nt++) {
            const int cbase = col0 + wn + nt * 8;
            float2 cn = *reinterpret_cast<const float2*>(&g_cnorm[cbase + tt * 2]);
            float d0 = __fmaf_rn(-2.f, acc[mt][nt][0], cn.x);
            float d1 = __fmaf_rn(-2.f, acc[mt][nt][1], cn.y);
            float d2 = __fmaf_rn(-2.f, acc[mt][nt][2], cn.x);
            float d3 = __fmaf_rn(-2.f, acc[mt][nt][3], cn.y);
            acc[mt][nt][0] = d0; acc[mt][nt][1] = d1;
            acc[mt][nt][2] = d2; acc[mt][nt][3] = d3;
            rmin[mt][0] = fminf(rmin[mt][0], fminf(d0, d1));
            rmin[mt][1] = fminf(rmin[mt][1], fminf(d2, d3));
        }
    // reduce mins over the 4 tt lanes sharing each row (xor on lane bits 0-1)
    #pragma unroll
    for (int mt = 0; mt < 2; mt++)
        #pragma unroll
        for (int h = 0; h < 2; h++) {
            #pragma unroll
            for (int off = 1; off < 4; off <<= 1)
                rmin[mt][h] = fminf(rmin[mt][h],
                                    __shfl_xor_sync(0xffffffffu, rmin[mt][h], off));
        }
    if (tt == 0) {
        #pragma unroll
        for (int mt = 0; mt < 2; mt++) {
            const int grow = row0 + wm + mt * 16 + r;
            atomicMin(&g_minu[grow],     fmap(rmin[mt][0]));
            atomicMin(&g_minu[grow + 8], fmap(rmin[mt][1]));
        }
    }

    // --- count candidates (exact f32 compare; +1e-4 absorbs bf16 asymmetry)
    if (t == 0) s_cnt = 0;
    float th[2][2];
    #pragma unroll
    for (int mt = 0; mt < 2; mt++)
        #pragma unroll
        for (int h = 0; h < 2; h++) th[mt][h] = rmin[mt][h] + (MARGIN + 1e-4f);

    int cnt = 0;
    #pragma unroll
    for (int mt = 0; mt < 2; mt++)
        #pragma unroll
        for (int nt = 0; nt < 8; nt++)
            #pragma unroll
            for (int q = 0; q < 4; q++)
                cnt += (acc[mt][nt][q] <= th[mt][q >> 1]) ? 1 : 0;

    // warp inclusive scan of cnt
    int pref = cnt;
    #pragma unroll
    for (int off = 1; off < 32; off <<= 1) {
        int v = __shfl_up_sync(0xffffffffu, pref, off);
        if (lane >= off) pref += v;
    }
    int excl = pref - cnt;
    __syncthreads();                         // s_cnt = 0 visible
    int wbase = 0;
    if (lane == 31) wbase = atomicAdd(&s_cnt, pref);   // pref@31 = warp total
    wbase = __shfl_sync(0xffffffffu, wbase, 31);
    __syncthreads();
    if (t == 0) s_base = s_cnt ? atomicAdd(&g_candCount, s_cnt) : 0;
    __syncthreads();
    int pos = s_base + wbase + excl;

    // --- emit (identical traversal order & predicate as the count)
    #pragma unroll
    for (int mt = 0; mt < 2; mt++)
        #pragma unroll
        for (int nt = 0; nt < 8; nt++)
            #pragma unroll
            for (int q = 0; q < 4; q++) {
                float d = acc[mt][nt][q];
                if (d <= th[mt][q >> 1]) {
                    if (pos < CAND_CAP) {
                        int grow = row0 + wm + mt * 16 + r + ((q >> 1) ? 8 : 0);
                        int k    = col0 + wn + nt * 8 + tt * 2 + (q & 1);
                        uint32_t dbits =
                            (uint32_t)__bfloat16_as_ushort(__float2bfloat16(d));
                        g_cand[pos] = ((unsigned long long)dbits << 32)
                                    | ((uint32_t)grow << 11) | (uint32_t)k;
                    }
                    pos++;
                }
            }
}

// ---------------- (5) filter2: global-margin test on candidate list ---------
__global__ void __launch_bounds__(256) filter2_kernel() {
    __shared__ int s_cnt, s_base;
    const int t = threadIdx.x, lane = t & 31;
    const int i = blockIdx.x * 256 + t;
    int total = g_candCount; if (total > CAND_CAP) total = CAND_CAP;

    bool pass = false;
    uint32_t nk = 0;
    if (i < total) {
        unsigned long long e = g_cand[i];
        nk = (uint32_t)e & 0x1FFFFFFu;
        int n = nk >> 11;
        float coarse = __bfloat162float(__ushort_as_bfloat16((unsigned short)(e >> 32)));
        pass = coarse <= funmap(g_minu[n]) + MARGIN;
    }
    if (t == 0) s_cnt = 0;
    unsigned bal = __ballot_sync(0xffffffffu, pass);
    __syncthreads();
    int wbase = 0;
    if (lane == 0 && bal) wbase = atomicAdd(&s_cnt, __popc(bal));
    wbase = __shfl_sync(0xffffffffu, wbase, 0);
    __syncthreads();
    if (t == 0) s_base = s_cnt ? atomicAdd(&g_rescCount, s_cnt) : 0;
    __syncthreads();
    if (pass) {
        int p = s_base + wbase + __popc(bal & ((1u << lane) - 1u));
        if (p < RESC_CAP) g_resc[p] = nk;
    }
}

// ---------------- (6) rescore: exact fp32 chain per survivor ----------------
// Computes zn inline from g_zt with the SAME ascending sequential chain the
// old znorm kernel used (bitwise identical, verified 6x).
__global__ void __launch_bounds__(256) rescore_kernel(const float* __restrict__ cb) {
    int i = blockIdx.x * blockDim.x + threadIdx.x;
    int cnt = g_rescCount; if (cnt > RESC_CAP) cnt = RESC_CAP;
    if (i >= cnt) return;
    uint32_t e = g_resc[i];
    int n = e >> 11, k = e & 2047;
    const float4* za4 = reinterpret_cast<const float4*>(g_zt + (size_t)n * DDIM);
    const float4* ca4 = reinterpret_cast<const float4*>(cb + (size_t)k * DDIM);
    float acc = 0.f, zn = 0.f;
    #pragma unroll 8
    for (int d4 = 0; d4 < DDIM / 4; d4++) {
        float4 a = za4[d4], c = ca4[d4];
        zn  = __fmaf_rn(a.x, a.x, zn);    // znorm chain (ascending d)
        zn  = __fmaf_rn(a.y, a.y, zn);
        zn  = __fmaf_rn(a.z, a.z, zn);
        zn  = __fmaf_rn(a.w, a.w, zn);
        acc = __fmaf_rn(a.x, c.x, acc);   // dot chain (ascending d)
        acc = __fmaf_rn(a.y, c.y, acc);
        acc = __fmaf_rn(a.z, c.z, acc);
        acc = __fmaf_rn(a.w, c.w, acc);
    }
    float dist = __fadd_rn(__fadd_rn(zn, g_cnorm[k]), -2.0f * acc);
    // dist > 0 (~256): float bits order-preserving; ties -> lowest k
    unsigned long long pk = ((unsigned long long)__float_as_uint(dist) << 32) | (unsigned)k;
    atomicMin(&g_best[n], pk);
}

// ---------------- (7) gather + STE (chain matched 5x) ----------------
__global__ void gather_kernel(const float* __restrict__ z,
                              const float* __restrict__ cb,
                              float* __restrict__ out) {
    int o4 = blockIdx.x * blockDim.x + threadIdx.x;
    int p4 = o4 & 255, d = (o4 >> 8) & 255, b = o4 >> 16;
    int p = p4 * 4, nb = b * HW + p;
    size_t off = ((size_t)(b * DDIM + d)) * HW + p;
    float4 zv = *reinterpret_cast<const float4*>(z + off);
    int k0 = (int)(g_best[nb + 0] & 0xffffffffu);
    int k1 = (int)(g_best[nb + 1] & 0xffffffffu);
    int k2 = (int)(g_best[nb + 2] & 0xffffffffu);
    int k3 = (int)(g_best[nb + 3] & 0xffffffffu);
    float q0 = cb[(size_t)k0 * DDIM + d];
    float q1 = cb[(size_t)k1 * DDIM + d];
    float q2 = cb[(size_t)k2 * DDIM + d];
    float q3 = cb[(size_t)k3 * DDIM + d];
    float4 r;
    r.x = __fadd_rn(zv.x, __fadd_rn(q0, -zv.x));
    r.y = __fadd_rn(zv.y, __fadd_rn(q1, -zv.y));
    r.z = __fadd_rn(zv.z, __fadd_rn(q2, -zv.z));
    r.w = __fadd_rn(zv.w, __fadd_rn(q3, -zv.w));
    *reinterpret_cast<float4*>(out + off) = r;
}

// ---------------------------------------------------------------------------
// mma stays launch #4 (profiler slot).
extern "C" void kernel_launch(void* const* d_in, const int* in_sizes, int n_in,
                              void* d_out, int out_size) {
    const float* z  = (const float*)d_in[0];
    const float* cb = (const float*)d_in[1];
    float* out = (float*)d_out;

    init_kernel<<<N_ROWS / 256, 256>>>();                    // 1
    cbcnorm_kernel<<<KCODES / 256, 256>>>(cb);               // 2
    transpose_kernel<<<dim3(256, 16), 256>>>(z);             // 3
    mma_kernel<<<dim3(N_ROWS / 128, KCODES / 128), 256>>>(); // 4 <- profiled
    filter2_kernel<<<CAND_CAP / 256, 256>>>();               // 5
    rescore_kernel<<<RESC_CAP / 256, 256>>>(cb);             // 6
    gather_kernel<<<(N_ROWS * DDIM / 4) / 256, 256>>>(z, cb, out); // 7
}

// round 9
// speedup vs baseline: 5.4357x; 1.2031x over previous
#include <cuda_runtime.h>
#include <cuda_bf16.h>
#include <cstdint>

// Shapes (fixed): z (16,256,32,32) fp32; codebook (2048,256) fp32; out like z.
#define N_ROWS 16384
#define DDIM   256
#define KCODES 2048
#define HW     1024
#define CAND_CAP (1 << 22)   // 4M coarse candidates
#define RESC_CAP (1 << 19)   // 512K survivors

// Margin: worst-case coarse error ~9e-4; 2.5e-3 validated in R7/R8.
#define MARGIN 2.5e-3f

// ---------------- device scratch (no mallocs allowed) ----------------
__device__ float              g_cnorm[KCODES];
__device__ uint32_t           g_minu[N_ROWS];
__device__ unsigned long long g_best[N_ROWS];
__device__ int                g_candCount;
__device__ int                g_rescCount;
__device__ unsigned long long g_cand[CAND_CAP];        // (coarse_bf16<<32)|(n<<11)|k
__device__ uint32_t           g_resc[RESC_CAP];        // (n<<11)|k survivors
__device__ float              g_zt [N_ROWS * DDIM];    // token-major fp32 z
__device__ __nv_bfloat16      g_ztb[N_ROWS * DDIM];    // token-major bf16 z
__device__ __nv_bfloat16      g_cbb[KCODES * DDIM];    // bf16 codebook

// ---------------- small helpers ----------------
__device__ __forceinline__ uint32_t cvt_bf16x2(float a, float b) {  // lo=a, hi=b
    uint32_t r;
    asm("cvt.rn.bf16x2.f32 %0, %1, %2;" : "=r"(r) : "f"(b), "f"(a));
    return r;
}
__device__ __forceinline__ uint32_t fmap(float f) {
    uint32_t b = __float_as_uint(f);
    return (b & 0x80000000u) ? ~b : (b | 0x80000000u);
}
__device__ __forceinline__ float funmap(uint32_t u) {
    uint32_t b = (u & 0x80000000u) ? (u & 0x7fffffffu) : ~u;
    return __uint_as_float(b);
}
__device__ __forceinline__ void ldsm4(uint32_t& r0, uint32_t& r1, uint32_t& r2,
                                      uint32_t& r3, uint32_t addr) {
    asm volatile("ldmatrix.sync.aligned.m8n8.x4.shared.b16 {%0,%1,%2,%3}, [%4];"
                 : "=r"(r0), "=r"(r1), "=r"(r2), "=r"(r3) : "r"(addr));
}
__device__ __forceinline__ uint32_t smem_u32(const void* p) {
    uint32_t a;
    asm("{ .reg .u64 t; cvta.to.shared.u64 t, %1; cvt.u32.u64 %0, t; }" : "=r"(a) : "l"(p));
    return a;
}
__device__ __forceinline__ void mma16816(float* c, uint32_t a0, uint32_t a1,
                                         uint32_t a2, uint32_t a3,
                                         uint32_t b0, uint32_t b1) {
    asm volatile(
        "mma.sync.aligned.m16n8k16.row.col.f32.bf16.bf16.f32 "
        "{%0,%1,%2,%3}, {%4,%5,%6,%7}, {%8,%9}, {%0,%1,%2,%3};"
        : "+f"(c[0]), "+f"(c[1]), "+f"(c[2]), "+f"(c[3])
        : "r"(a0), "r"(a1), "r"(a2), "r"(a3), "r"(b0), "r"(b1));
}
__device__ __forceinline__ void cp16(uint32_t dst, const void* src) {
    asm volatile("cp.async.cg.shared.global [%0], [%1], 16;" :: "r"(dst), "l"(src));
}

// ---------------- (1) init per-replay state ----------------
__global__ void init_kernel() {
    int n = blockIdx.x * blockDim.x + threadIdx.x;
    if (n >= N_ROWS) return;
    g_minu[n] = 0xFFFFFFFFu;
    g_best[n] = 0xFFFFFFFFFFFFFFFFull;
    if (n == 0) { g_candCount = 0; g_rescCount = 0; }
}

// ---------------- (2) codebook: bf16 convert + exact sequential cnorm -------
__global__ void cbcnorm_kernel(const float* __restrict__ cb) {
    int k = blockIdx.x * blockDim.x + threadIdx.x;
    if (k >= KCODES) return;
    const float4* row4 = reinterpret_cast<const float4*>(cb + (size_t)k * DDIM);
    uint32_t* out = reinterpret_cast<uint32_t*>(g_cbb + (size_t)k * DDIM);
    float s = 0.f;
    #pragma unroll 4
    for (int d4 = 0; d4 < DDIM / 4; d4++) {
        float4 v = row4[d4];
        s = __fmaf_rn(v.x, v.x, s);   // sequential chain (matched JAX 6x)
        s = __fmaf_rn(v.y, v.y, s);
        s = __fmaf_rn(v.z, v.z, s);
        s = __fmaf_rn(v.w, v.w, s);
        out[d4 * 2 + 0] = cvt_bf16x2(v.x, v.y);
        out[d4 * 2 + 1] = cvt_bf16x2(v.z, v.w);
    }
    g_cnorm[k] = s;
}

// ---------------- (3) transpose z -> token-major fp32 + bf16 ----------------
__global__ void transpose_kernel(const float* __restrict__ z) {
    __shared__ float ts[32][33];
    int t = threadIdx.x, tx = t & 31, ty = t >> 5;   // 32 x 8
    int pt = blockIdx.x & 31, dt = blockIdx.x >> 5;
    int b  = blockIdx.y;
    int p0 = pt * 32, d0 = dt * 32;
    #pragma unroll
    for (int i = 0; i < 4; i++) {
        int d = d0 + ty + i * 8;
        ts[ty + i * 8][tx] = z[((size_t)(b * DDIM + d)) * HW + p0 + tx];
    }
    __syncthreads();
    #pragma unroll
    for (int i = 0; i < 4; i++) {
        int n = b * HW + p0 + ty + i * 8;
        float v = ts[tx][ty + i * 8];
        g_zt [(size_t)n * DDIM + d0 + tx] = v;
        g_ztb[(size_t)n * DDIM + d0 + tx] = __float2bfloat16(v);
    }
}

// ---------------- (4) coarse GEMM (cp.async double-buffered) + emission -----
#define PITCH 72
#define A_BYTES (128 * PITCH * 2)        // 18432
#define STAGE_BYTES (2 * A_BYTES)        // 36864 (A + B per stage)
#define MMA_SMEM (2 * STAGE_BYTES)       // 73728 dynamic

__global__ void __launch_bounds__(256, 2) mma_kernel() {
    extern __shared__ __align__(16) char dsm[];
    __shared__ int s_cnt, s_base;

    const int t = threadIdx.x, wid = t >> 5, lane = t & 31;
    const int row0 = blockIdx.x * 128, col0 = blockIdx.y * 128;
    const int wm = (wid & 3) * 32;
    const int wn = (wid >> 2) * 64;
    const int r  = lane >> 2, tt = lane & 3;
    const int grp = lane >> 3, l7 = lane & 7;

    const int a_row = (grp & 1) * 8 + l7, a_k = (grp & 2) * 4;
    const int b_row = (grp & 2) * 4 + l7, b_k = (grp & 1) * 8;
    const uint32_t sbase = smem_u32(dsm);
    uint32_t aOff[2], bOff[4];                   // stage-relative
    #pragma unroll
    for (int mt = 0; mt < 2; mt++)
        aOff[mt] = ((wm + mt * 16 + a_row) * PITCH + a_k) * 2;
    #pragma unroll
    for (int p = 0; p < 4; p++)
        bOff[p] = A_BYTES + ((wn + p * 16 + b_row) * PITCH + b_k) * 2;

    float acc[2][8][4];
    #pragma unroll
    for (int mt = 0; mt < 2; mt++)
        #pragma unroll
        for (int nt = 0; nt < 8; nt++)
            #pragma unroll
            for (int q = 0; q < 4; q++) acc[mt][nt][q] = 0.f;

    // prefetch one K-chunk (64 halves) into stage ch&1
    auto prefetch = [&](int ch) {
        const int s = ch & 1, cd0 = ch * 64;
        const uint32_t abuf = sbase + s * STAGE_BYTES;
        const uint32_t bbuf = abuf + A_BYTES;
        #pragma unroll
        for (int it = 0; it < 4; it++) {
            int idx = it * 256 + t;
            int rr = idx >> 3, k8 = (idx & 7) * 8;
            uint32_t off = (rr * PITCH + k8) * 2;
            cp16(abuf + off, &g_ztb[(size_t)(row0 + rr) * DDIM + cd0 + k8]);
            cp16(bbuf + off, &g_cbb[(size_t)(col0 + rr) * DDIM + cd0 + k8]);
        }
        asm volatile("cp.async.commit_group;" ::: "memory");
    };

    prefetch(0);
    for (int ch = 0; ch < 4; ch++) {
        if (ch < 3) {
            prefetch(ch + 1);
            asm volatile("cp.async.wait_group 1;" ::: "memory");
        } else {
            asm volatile("cp.async.wait_group 0;" ::: "memory");
        }
        __syncthreads();                      // stage ch&1 visible to all
        const uint32_t sb = sbase + (ch & 1) * STAGE_BYTES;
        #pragma unroll
        for (int ks = 0; ks < 4; ks++) {
            const uint32_t koff = ks * 32;
            uint32_t A0[4], A1[4];
            ldsm4(A0[0], A0[1], A0[2], A0[3], sb + aOff[0] + koff);
            ldsm4(A1[0], A1[1], A1[2], A1[3], sb + aOff[1] + koff);
            #pragma unroll
            for (int p = 0; p < 4; p++) {
                uint32_t B[4];
                ldsm4(B[0], B[1], B[2], B[3], sb + bOff[p] + koff);
                mma16816(acc[0][2 * p],     A0[0], A0[1], A0[2], A0[3], B[0], B[1]);
                mma16816(acc[0][2 * p + 1], A0[0], A0[1], A0[2], A0[3], B[2], B[3]);
                mma16816(acc[1][2 * p],     A1[0], A1[1], A1[2], A1[3], B[0], B[1]);
                mma16816(acc[1][2 * p + 1], A1[0], A1[1], A1[2], A1[3], B[2], B[3]);
            }
        }
        __syncthreads();                      // done reading before overwrite
    }

    // --- epilogue: coarse = cnorm - 2*dot; warp row mins; emission ---
    float rmin[2][2];
    #pragma unroll
    for (int mt = 0; mt < 2; mt++) { rmin[mt][0] = 3.4e38f; rmin[mt][1] = 3.4e38f; }
    #pragma unroll
    for (int mt = 0; mt < 2; mt++)
        #pragma unroll
        for (int nt = 0; nt < 8; nt++) {
            const int cbase = col0 + wn + nt * 8;
            float2 cn = *reinterpret_cast<const float2*>(&g_cnorm[cbase + tt * 2]);
            float d0 = __fmaf_rn(-2.f, acc[mt][nt][0], cn.x);
            float d1 = __fmaf_rn(-2.f, acc[mt][nt][1], cn.y);
            float d2 = __fmaf_rn(-2.f, acc[mt][nt][2], cn.x);
            float d3 = __fmaf_rn(-2.f, acc[mt][nt][3], cn.y);
            acc[mt][nt][0] = d0; acc[mt][nt][1] = d1;
            acc[mt][nt][2] = d2; acc[mt][nt][3] = d3;
            rmin[mt][0] = fminf(rmin[mt][0], fminf(d0, d1));
            rmin[mt][1] = fminf(rmin[mt][1], fminf(d2, d3));
        }
    #pragma unroll
    for (int mt = 0; mt < 2; mt++)
        #pragma unroll
        for (int h = 0; h < 2; h++)
            #pragma unroll
            for (int off = 1; off < 4; off <<= 1)
                rmin[mt][h] = fminf(rmin[mt][h],
                                    __shfl_xor_sync(0xffffffffu, rmin[mt][h], off));

    // publish mins; old global value (pre-update) tightens the local threshold
    float gmv[2][2];
    if (tt == 0) {
        #pragma unroll
        for (int mt = 0; mt < 2; mt++) {
            const int grow = row0 + wm + mt * 16 + r;
            uint32_t o0 = atomicMin(&g_minu[grow],     fmap(rmin[mt][0]));
            uint32_t o1 = atomicMin(&g_minu[grow + 8], fmap(rmin[mt][1]));
            gmv[mt][0] = funmap(o0);   // NaN if untouched; fminf ignores NaN
            gmv[mt][1] = funmap(o1);
        }
    }
    const int src = lane & ~3;
    float th[2][2];
    #pragma unroll
    for (int mt = 0; mt < 2; mt++)
        #pragma unroll
        for (int h = 0; h < 2; h++) {
            float g = __shfl_sync(0xffffffffu, gmv[mt][h], src);
            th[mt][h] = fminf(rmin[mt][h], g) + (MARGIN + 1e-4f);
        }

    if (t == 0) s_cnt = 0;
    int cnt = 0;
    #pragma unroll
    for (int mt = 0; mt < 2; mt++)
        #pragma unroll
        for (int nt = 0; nt < 8; nt++)
            #pragma unroll
            for (int q = 0; q < 4; q++)
                cnt += (acc[mt][nt][q] <= th[mt][q >> 1]) ? 1 : 0;

    int pref = cnt;
    #pragma unroll
    for (int off = 1; off < 32; off <<= 1) {
        int v = __shfl_up_sync(0xffffffffu, pref, off);
        if (lane >= off) pref += v;
    }
    int excl = pref - cnt;
    __syncthreads();
    int wbase = 0;
    if (lane == 31) wbase = atomicAdd(&s_cnt, pref);
    wbase = __shfl_sync(0xffffffffu, wbase, 31);
    __syncthreads();
    if (t == 0) s_base = s_cnt ? atomicAdd(&g_candCount, s_cnt) : 0;
    __syncthreads();
    int pos = s_base + wbase + excl;

    #pragma unroll
    for (int mt = 0; mt < 2; mt++)
        #pragma unroll
        for (int nt = 0; nt < 8; nt++)
            #pragma unroll
            for (int q = 0; q < 4; q++) {
                float d = acc[mt][nt][q];
                if (d <= th[mt][q >> 1]) {
                    if (pos < CAND_CAP) {
                        int grow = row0 + wm + mt * 16 + r + ((q >> 1) ? 8 : 0);
                        int k    = col0 + wn + nt * 8 + tt * 2 + (q & 1);
                        uint32_t dbits =
                            (uint32_t)__bfloat16_as_ushort(__float2bfloat16(d));
                        g_cand[pos] = ((unsigned long long)dbits << 32)
                                    | ((uint32_t)grow << 11) | (uint32_t)k;
                    }
                    pos++;
                }
            }
}

// ---------------- (5) filter2: global-margin test on candidate list ---------
__global__ void __launch_bounds__(256) filter2_kernel() {
    __shared__ int s_cnt, s_base;
    const int t = threadIdx.x, lane = t & 31;
    const int i = blockIdx.x * 256 + t;
    int total = g_candCount; if (total > CAND_CAP) total = CAND_CAP;

    bool pass = false;
    uint32_t nk = 0;
    if (i < total) {
        unsigned long long e = g_cand[i];
        nk = (uint32_t)e & 0x1FFFFFFu;
        int n = nk >> 11;
        float coarse = __bfloat162float(__ushort_as_bfloat16((unsigned short)(e >> 32)));
        pass = coarse <= funmap(g_minu[n]) + MARGIN;
    }
    if (t == 0) s_cnt = 0;
    unsigned bal = __ballot_sync(0xffffffffu, pass);
    __syncthreads();
    int wbase = 0;
    if (lane == 0 && bal) wbase = atomicAdd(&s_cnt, __popc(bal));
    wbase = __shfl_sync(0xffffffffu, wbase, 0);
    __syncthreads();
    if (t == 0) s_base = s_cnt ? atomicAdd(&g_rescCount, s_cnt) : 0;
    __syncthreads();
    if (pass) {
        int p = s_base + wbase + __popc(bal & ((1u << lane) - 1u));
        if (p < RESC_CAP) g_resc[p] = nk;
    }
}

// ---------------- (6) rescore: exact fp32 chain per survivor ----------------
__global__ void __launch_bounds__(256) rescore_kernel(const float* __restrict__ cb) {
    int i = blockIdx.x * blockDim.x + threadIdx.x;
    int cnt = g_rescCount; if (cnt > RESC_CAP) cnt = RESC_CAP;
    if (i >= cnt) return;
    uint32_t e = g_resc[i];
    int n = e >> 11, k = e & 2047;
    const float4* za4 = reinterpret_cast<const float4*>(g_zt + (size_t)n * DDIM);
    const float4* ca4 = reinterpret_cast<const float4*>(cb + (size_t)k * DDIM);
    float acc = 0.f, zn = 0.f;
    #pragma unroll 8
    for (int d4 = 0; d4 < DDIM / 4; d4++) {
        float4 a = za4[d4], c = ca4[d4];
        zn  = __fmaf_rn(a.x, a.x, zn);    // znorm chain (ascending d, verified)
        zn  = __fmaf_rn(a.y, a.y, zn);
        zn  = __fmaf_rn(a.z, a.z, zn);
        zn  = __fmaf_rn(a.w, a.w, zn);
        acc = __fmaf_rn(a.x, c.x, acc);   // dot chain (ascending d, verified)
        acc = __fmaf_rn(a.y, c.y, acc);
        acc = __fmaf_rn(a.z, c.z, acc);
        acc = __fmaf_rn(a.w, c.w, acc);
    }
    float dist = __fadd_rn(__fadd_rn(zn, g_cnorm[k]), -2.0f * acc);
    unsigned long long pk = ((unsigned long long)__float_as_uint(dist) << 32) | (unsigned)k;
    atomicMin(&g_best[n], pk);
}

// ---------------- (7) gather + STE with smem-staged codebook rows ----------
#define GT 32   // tokens per CTA (divides 1024 -> single b per CTA)

__global__ void __launch_bounds__(256) gather_kernel(const float* __restrict__ z,
                                                     const float* __restrict__ cb,
                                                     float* __restrict__ out) {
    __shared__ float cbrow[GT][DDIM + 1];   // pitch 257: conflict-free reads
    __shared__ int ks[GT];
    const int t = threadIdx.x;
    const int n0 = blockIdx.x * GT;
    const int b = n0 >> 10, p0 = n0 & 1023;

    if (t < GT) ks[t] = (int)(g_best[n0 + t] & 0xffffffffu);
    __syncthreads();

    // stage 32 codebook rows, coalesced float4 reads (scalar smem stores)
    #pragma unroll
    for (int it = 0; it < (GT * DDIM / 4) / 256; it++) {   // 8 iters
        int slot = it * 256 + t;
        int tok = slot >> 6, c4 = slot & 63;
        float4 v = reinterpret_cast<const float4*>(cb + (size_t)ks[tok] * DDIM)[c4];
        cbrow[tok][c4 * 4 + 0] = v.x;
        cbrow[tok][c4 * 4 + 1] = v.y;
        cbrow[tok][c4 * 4 + 2] = v.z;
        cbrow[tok][c4 * 4 + 3] = v.w;
    }
    __syncthreads();

    // write outputs: 256 d x 8 p4-float4, coalesced on z/out
    const size_t zbase = (size_t)b * DDIM * HW + p0;
    #pragma unroll
    for (int it = 0; it < 8; it++) {
        int slot = it * 256 + t;
        int d = slot >> 3, p4 = slot & 7;
        size_t off = zbase + (size_t)d * HW + p4 * 4;
        float4 zv = *reinterpret_cast<const float4*>(z + off);
        float q0 = cbrow[p4 * 4 + 0][d];
        float q1 = cbrow[p4 * 4 + 1][d];
        float q2 = cbrow[p4 * 4 + 2][d];
        float q3 = cbrow[p4 * 4 + 3][d];
        float4 r;
        r.x = __fadd_rn(zv.x, __fadd_rn(q0, -zv.x));   // STE chain (matched 6x)
        r.y = __fadd_rn(zv.y, __fadd_rn(q1, -zv.y));
        r.z = __fadd_rn(zv.z, __fadd_rn(q2, -zv.z));
        r.w = __fadd_rn(zv.w, __fadd_rn(q3, -zv.w));
        *reinterpret_cast<float4*>(out + off) = r;
    }
}

// ---------------------------------------------------------------------------
// mma stays launch #4 (profiler slot).
extern "C" void kernel_launch(void* const* d_in, const int* in_sizes, int n_in,
                              void* d_out, int out_size) {
    const float* z  = (const float*)d_in[0];
    const float* cb = (const float*)d_in[1];
    float* out = (float*)d_out;

    cudaFuncSetAttribute(mma_kernel,
                         cudaFuncAttributeMaxDynamicSharedMemorySize, MMA_SMEM);

    init_kernel<<<N_ROWS / 256, 256>>>();                              // 1
    cbcnorm_kernel<<<KCODES / 256, 256>>>(cb);                         // 2
    transpose_kernel<<<dim3(256, 16), 256>>>(z);                       // 3
    mma_kernel<<<dim3(N_ROWS / 128, KCODES / 128), 256, MMA_SMEM>>>(); // 4 <- profiled
    filter2_kernel<<<CAND_CAP / 256, 256>>>();                         // 5
    rescore_kernel<<<RESC_CAP / 256, 256>>>(cb);                       // 6
    gather_kernel<<<N_ROWS / GT, 256>>>(z, cb, out);                   // 7
}

// round 10
// speedup vs baseline: 5.5834x; 1.0272x over previous
#include <cuda_runtime.h>
#include <cuda_bf16.h>
#include <cstdint>

// Shapes (fixed): z (16,256,32,32) fp32; codebook (2048,256) fp32; out like z.
#define N_ROWS 16384
#define DDIM   256
#define KCODES 2048
#define HW     1024
#define CAND_CAP (1 << 22)   // 4M coarse candidates
#define RESC_CAP (1 << 19)   // 512K survivors

// Margin: worst-case coarse error ~9e-4; 2.5e-3 validated in R7/R8/R9.
#define MARGIN 2.5e-3f

// ---------------- device scratch (no mallocs allowed) ----------------
__device__ float              g_cnorm[KCODES];
__device__ uint32_t           g_minu[N_ROWS];
__device__ unsigned long long g_best[N_ROWS];
__device__ int                g_candCount;
__device__ int                g_rescCount;
__device__ unsigned long long g_cand[CAND_CAP];        // (coarse_bf16<<32)|(n<<11)|k
__device__ uint32_t           g_resc[RESC_CAP];        // (n<<11)|k survivors
__device__ float              g_zt [N_ROWS * DDIM];    // token-major fp32 z
__device__ __nv_bfloat16      g_ztb[N_ROWS * DDIM];    // token-major bf16 z
__device__ __nv_bfloat16      g_cbb[KCODES * DDIM];    // bf16 codebook

// ---------------- small helpers ----------------
__device__ __forceinline__ uint32_t cvt_bf16x2(float a, float b) {  // lo=a, hi=b
    uint32_t r;
    asm("cvt.rn.bf16x2.f32 %0, %1, %2;" : "=r"(r) : "f"(b), "f"(a));
    return r;
}
__device__ __forceinline__ uint32_t fmap(float f) {
    uint32_t b = __float_as_uint(f);
    return (b & 0x80000000u) ? ~b : (b | 0x80000000u);
}
__device__ __forceinline__ float funmap(uint32_t u) {
    uint32_t b = (u & 0x80000000u) ? (u & 0x7fffffffu) : ~u;
    return __uint_as_float(b);
}
__device__ __forceinline__ void ldsm4(uint32_t& r0, uint32_t& r1, uint32_t& r2,
                                      uint32_t& r3, uint32_t addr) {
    asm volatile("ldmatrix.sync.aligned.m8n8.x4.shared.b16 {%0,%1,%2,%3}, [%4];"
                 : "=r"(r0), "=r"(r1), "=r"(r2), "=r"(r3) : "r"(addr));
}
__device__ __forceinline__ uint32_t smem_u32(const void* p) {
    uint32_t a;
    asm("{ .reg .u64 t; cvta.to.shared.u64 t, %1; cvt.u32.u64 %0, t; }" : "=r"(a) : "l"(p));
    return a;
}
__device__ __forceinline__ void mma16816(float* c, uint32_t a0, uint32_t a1,
                                         uint32_t a2, uint32_t a3,
                                         uint32_t b0, uint32_t b1) {
    asm volatile(
        "mma.sync.aligned.m16n8k16.row.col.f32.bf16.bf16.f32 "
        "{%0,%1,%2,%3}, {%4,%5,%6,%7}, {%8,%9}, {%0,%1,%2,%3};"
        : "+f"(c[0]), "+f"(c[1]), "+f"(c[2]), "+f"(c[3])
        : "r"(a0), "r"(a1), "r"(a2), "r"(a3), "r"(b0), "r"(b1));
}
__device__ __forceinline__ void cp16(uint32_t dst, const void* src) {
    asm volatile("cp.async.cg.shared.global [%0], [%1], 16;" :: "r"(dst), "l"(src));
}

// ---------------- (1) init per-replay state ----------------
__global__ void init_kernel() {
    int n = blockIdx.x * blockDim.x + threadIdx.x;
    if (n >= N_ROWS) return;
    g_minu[n] = 0xFFFFFFFFu;
    g_best[n] = 0xFFFFFFFFFFFFFFFFull;
    if (n == 0) { g_candCount = 0; g_rescCount = 0; }
}

// ---------------- (2) codebook: bf16 convert + exact sequential cnorm -------
__global__ void cbcnorm_kernel(const float* __restrict__ cb) {
    int k = blockIdx.x * blockDim.x + threadIdx.x;
    if (k >= KCODES) return;
    const float4* row4 = reinterpret_cast<const float4*>(cb + (size_t)k * DDIM);
    uint32_t* out = reinterpret_cast<uint32_t*>(g_cbb + (size_t)k * DDIM);
    float s = 0.f;
    #pragma unroll 4
    for (int d4 = 0; d4 < DDIM / 4; d4++) {
        float4 v = row4[d4];
        s = __fmaf_rn(v.x, v.x, s);   // sequential chain (matched JAX 7x)
        s = __fmaf_rn(v.y, v.y, s);
        s = __fmaf_rn(v.z, v.z, s);
        s = __fmaf_rn(v.w, v.w, s);
        out[d4 * 2 + 0] = cvt_bf16x2(v.x, v.y);
        out[d4 * 2 + 1] = cvt_bf16x2(v.z, v.w);
    }
    g_cnorm[k] = s;
}

// ---------------- (3) transpose z -> token-major fp32 + bf16 ----------------
__global__ void transpose_kernel(const float* __restrict__ z) {
    __shared__ float ts[32][33];
    int t = threadIdx.x, tx = t & 31, ty = t >> 5;   // 32 x 8
    int pt = blockIdx.x & 31, dt = blockIdx.x >> 5;
    int b  = blockIdx.y;
    int p0 = pt * 32, d0 = dt * 32;
    #pragma unroll
    for (int i = 0; i < 4; i++) {
        int d = d0 + ty + i * 8;
        ts[ty + i * 8][tx] = z[((size_t)(b * DDIM + d)) * HW + p0 + tx];
    }
    __syncthreads();
    #pragma unroll
    for (int i = 0; i < 4; i++) {
        int n = b * HW + p0 + ty + i * 8;
        float v = ts[tx][ty + i * 8];
        g_zt [(size_t)n * DDIM + d0 + tx] = v;
        g_ztb[(size_t)n * DDIM + d0 + tx] = __float2bfloat16(v);
    }
}

// ---------------- (4) coarse GEMM (cp.async double-buffered) + emission -----
#define PITCH 72
#define A_BYTES (128 * PITCH * 2)        // 18432
#define STAGE_BYTES (2 * A_BYTES)        // 36864 (A + B per stage)
#define MMA_SMEM (2 * STAGE_BYTES)       // 73728 dynamic

__global__ void __launch_bounds__(256, 2) mma_kernel() {
    extern __shared__ __align__(16) char dsm[];
    __shared__ int s_cnt, s_base;

    const int t = threadIdx.x, wid = t >> 5, lane = t & 31;
    const int row0 = blockIdx.x * 128, col0 = blockIdx.y * 128;
    const int wm = (wid & 3) * 32;
    const int wn = (wid >> 2) * 64;
    const int r  = lane >> 2, tt = lane & 3;
    const int grp = lane >> 3, l7 = lane & 7;

    const int a_row = (grp & 1) * 8 + l7, a_k = (grp & 2) * 4;
    const int b_row = (grp & 2) * 4 + l7, b_k = (grp & 1) * 8;
    const uint32_t sbase = smem_u32(dsm);
    uint32_t aOff[2], bOff[4];                   // stage-relative
    #pragma unroll
    for (int mt = 0; mt < 2; mt++)
        aOff[mt] = ((wm + mt * 16 + a_row) * PITCH + a_k) * 2;
    #pragma unroll
    for (int p = 0; p < 4; p++)
        bOff[p] = A_BYTES + ((wn + p * 16 + b_row) * PITCH + b_k) * 2;

    float acc[2][8][4];
    #pragma unroll
    for (int mt = 0; mt < 2; mt++)
        #pragma unroll
        for (int nt = 0; nt < 8; nt++)
            #pragma unroll
            for (int q = 0; q < 4; q++) acc[mt][nt][q] = 0.f;

    auto prefetch = [&](int ch) {
        const int s = ch & 1, cd0 = ch * 64;
        const uint32_t abuf = sbase + s * STAGE_BYTES;
        const uint32_t bbuf = abuf + A_BYTES;
        #pragma unroll
        for (int it = 0; it < 4; it++) {
            int idx = it * 256 + t;
            int rr = idx >> 3, k8 = (idx & 7) * 8;
            uint32_t off = (rr * PITCH + k8) * 2;
            cp16(abuf + off, &g_ztb[(size_t)(row0 + rr) * DDIM + cd0 + k8]);
            cp16(bbuf + off, &g_cbb[(size_t)(col0 + rr) * DDIM + cd0 + k8]);
        }
        asm volatile("cp.async.commit_group;" ::: "memory");
    };

    prefetch(0);
    for (int ch = 0; ch < 4; ch++) {
        if (ch < 3) {
            prefetch(ch + 1);
            asm volatile("cp.async.wait_group 1;" ::: "memory");
        } else {
            asm volatile("cp.async.wait_group 0;" ::: "memory");
        }
        __syncthreads();
        const uint32_t sb = sbase + (ch & 1) * STAGE_BYTES;
        #pragma unroll
        for (int ks = 0; ks < 4; ks++) {
            const uint32_t koff = ks * 32;
            uint32_t A0[4], A1[4];
            ldsm4(A0[0], A0[1], A0[2], A0[3], sb + aOff[0] + koff);
            ldsm4(A1[0], A1[1], A1[2], A1[3], sb + aOff[1] + koff);
            #pragma unroll
            for (int p = 0; p < 4; p++) {
                uint32_t B[4];
                ldsm4(B[0], B[1], B[2], B[3], sb + bOff[p] + koff);
                mma16816(acc[0][2 * p],     A0[0], A0[1], A0[2], A0[3], B[0], B[1]);
                mma16816(acc[0][2 * p + 1], A0[0], A0[1], A0[2], A0[3], B[2], B[3]);
                mma16816(acc[1][2 * p],     A1[0], A1[1], A1[2], A1[3], B[0], B[1]);
                mma16816(acc[1][2 * p + 1], A1[0], A1[1], A1[2], A1[3], B[2], B[3]);
            }
        }
        __syncthreads();
    }

    // --- epilogue: coarse = cnorm - 2*dot; warp row mins; emission ---
    float rmin[2][2];
    #pragma unroll
    for (int mt = 0; mt < 2; mt++) { rmin[mt][0] = 3.4e38f; rmin[mt][1] = 3.4e38f; }
    #pragma unroll
    for (int mt = 0; mt < 2; mt++)
        #pragma unroll
        for (int nt = 0; nt < 8; nt++) {
            const int cbase = col0 + wn + nt * 8;
            float2 cn = *reinterpret_cast<const float2*>(&g_cnorm[cbase + tt * 2]);
            float d0 = __fmaf_rn(-2.f, acc[mt][nt][0], cn.x);
            float d1 = __fmaf_rn(-2.f, acc[mt][nt][1], cn.y);
            float d2 = __fmaf_rn(-2.f, acc[mt][nt][2], cn.x);
            float d3 = __fmaf_rn(-2.f, acc[mt][nt][3], cn.y);
            acc[mt][nt][0] = d0; acc[mt][nt][1] = d1;
            acc[mt][nt][2] = d2; acc[mt][nt][3] = d3;
            rmin[mt][0] = fminf(rmin[mt][0], fminf(d0, d1));
            rmin[mt][1] = fminf(rmin[mt][1], fminf(d2, d3));
        }
    #pragma unroll
    for (int mt = 0; mt < 2; mt++)
        #pragma unroll
        for (int h = 0; h < 2; h++)
            #pragma unroll
            for (int off = 1; off < 4; off <<= 1)
                rmin[mt][h] = fminf(rmin[mt][h],
                                    __shfl_xor_sync(0xffffffffu, rmin[mt][h], off));

    float gmv[2][2];
    if (tt == 0) {
        #pragma unroll
        for (int mt = 0; mt < 2; mt++) {
            const int grow = row0 + wm + mt * 16 + r;
            uint32_t o0 = atomicMin(&g_minu[grow],     fmap(rmin[mt][0]));
            uint32_t o1 = atomicMin(&g_minu[grow + 8], fmap(rmin[mt][1]));
            gmv[mt][0] = funmap(o0);   // NaN if untouched; fminf ignores NaN
            gmv[mt][1] = funmap(o1);
        }
    }
    const int src = lane & ~3;
    float th[2][2];
    #pragma unroll
    for (int mt = 0; mt < 2; mt++)
        #pragma unroll
        for (int h = 0; h < 2; h++) {
            float g = __shfl_sync(0xffffffffu, gmv[mt][h], src);
            th[mt][h] = fminf(rmin[mt][h], g) + (MARGIN + 1e-4f);
        }

    if (t == 0) s_cnt = 0;
    int cnt = 0;
    #pragma unroll
    for (int mt = 0; mt < 2; mt++)
        #pragma unroll
        for (int nt = 0; nt < 8; nt++)
            #pragma unroll
            for (int q = 0; q < 4; q++)
                cnt += (acc[mt][nt][q] <= th[mt][q >> 1]) ? 1 : 0;

    int pref = cnt;
    #pragma unroll
    for (int off = 1; off < 32; off <<= 1) {
        int v = __shfl_up_sync(0xffffffffu, pref, off);
        if (lane >= off) pref += v;
    }
    int excl = pref - cnt;
    __syncthreads();
    int wbase = 0;
    if (lane == 31) wbase = atomicAdd(&s_cnt, pref);
    wbase = __shfl_sync(0xffffffffu, wbase, 31);
    __syncthreads();
    if (t == 0) s_base = s_cnt ? atomicAdd(&g_candCount, s_cnt) : 0;
    __syncthreads();
    int pos = s_base + wbase + excl;

    #pragma unroll
    for (int mt = 0; mt < 2; mt++)
        #pragma unroll
        for (int nt = 0; nt < 8; nt++)
            #pragma unroll
            for (int q = 0; q < 4; q++) {
                float d = acc[mt][nt][q];
                if (d <= th[mt][q >> 1]) {
                    if (pos < CAND_CAP) {
                        int grow = row0 + wm + mt * 16 + r + ((q >> 1) ? 8 : 0);
                        int k    = col0 + wn + nt * 8 + tt * 2 + (q & 1);
                        uint32_t dbits =
                            (uint32_t)__bfloat16_as_ushort(__float2bfloat16(d));
                        g_cand[pos] = ((unsigned long long)dbits << 32)
                                    | ((uint32_t)grow << 11) | (uint32_t)k;
                    }
                    pos++;
                }
            }
}

// ---------------- (5) filter2: grid-stride global-margin test ---------------
#define F2_GRID 512

__global__ void __launch_bounds__(256) filter2_kernel() {
    const int lane = threadIdx.x & 31;
    int total = g_candCount; if (total > CAND_CAP) total = CAND_CAP;

    for (int i = blockIdx.x * 256 + threadIdx.x; ; i += F2_GRID * 256) {
        // whole warp must iterate together for ballot correctness
        if (__all_sync(0xffffffffu, i >= total)) break;
        bool pass = false;
        uint32_t nk = 0;
        if (i < total) {
            unsigned long long e = g_cand[i];
            nk = (uint32_t)e & 0x1FFFFFFu;
            int n = nk >> 11;
            float coarse =
                __bfloat162float(__ushort_as_bfloat16((unsigned short)(e >> 32)));
            pass = coarse <= funmap(g_minu[n]) + MARGIN;
        }
        unsigned bal = __ballot_sync(0xffffffffu, pass);
        if (bal) {
            int wbase = 0;
            if (lane == 0) wbase = atomicAdd(&g_rescCount, __popc(bal));
            wbase = __shfl_sync(0xffffffffu, wbase, 0);
            if (pass) {
                int p = wbase + __popc(bal & ((1u << lane) - 1u));
                if (p < RESC_CAP) g_resc[p] = nk;
            }
        }
    }
}

// ---------------- (6) rescore: grid-stride, exact fp32 chain ----------------
#define RS_GRID 1024

__global__ void __launch_bounds__(256) rescore_kernel(const float* __restrict__ cb) {
    int cnt = g_rescCount; if (cnt > RESC_CAP) cnt = RESC_CAP;
    for (int i = blockIdx.x * 256 + threadIdx.x; i < cnt; i += RS_GRID * 256) {
        uint32_t e = g_resc[i];
        int n = e >> 11, k = e & 2047;
        const float4* za4 = reinterpret_cast<const float4*>(g_zt + (size_t)n * DDIM);
        const float4* ca4 = reinterpret_cast<const float4*>(cb + (size_t)k * DDIM);
        float acc = 0.f, zn = 0.f;
        #pragma unroll 8
        for (int d4 = 0; d4 < DDIM / 4; d4++) {
            float4 a = za4[d4], c = ca4[d4];
            zn  = __fmaf_rn(a.x, a.x, zn);    // znorm chain (ascending d, verified)
            zn  = __fmaf_rn(a.y, a.y, zn);
            zn  = __fmaf_rn(a.z, a.z, zn);
            zn  = __fmaf_rn(a.w, a.w, zn);
            acc = __fmaf_rn(a.x, c.x, acc);   // dot chain (ascending d, verified)
            acc = __fmaf_rn(a.y, c.y, acc);
            acc = __fmaf_rn(a.z, c.z, acc);
            acc = __fmaf_rn(a.w, c.w, acc);
        }
        float dist = __fadd_rn(__fadd_rn(zn, g_cnorm[k]), -2.0f * acc);
        unsigned long long pk =
            ((unsigned long long)__float_as_uint(dist) << 32) | (unsigned)k;
        atomicMin(&g_best[n], pk);
    }
}

// ---------------- (7) gather + STE with smem-staged codebook rows ----------
#define GT 32   // tokens per CTA

__global__ void __launch_bounds__(256) gather_kernel(const float* __restrict__ z,
                                                     const float* __restrict__ cb,
                                                     float* __restrict__ out) {
    __shared__ float cbrow[GT][DDIM + 1];
    __shared__ int ks[GT];
    const int t = threadIdx.x;
    const int n0 = blockIdx.x * GT;
    const int b = n0 >> 10, p0 = n0 & 1023;

    if (t < GT) ks[t] = (int)(g_best[n0 + t] & 0xffffffffu);
    __syncthreads();

    #pragma unroll
    for (int it = 0; it < (GT * DDIM / 4) / 256; it++) {
        int slot = it * 256 + t;
        int tok = slot >> 6, c4 = slot & 63;
        float4 v = reinterpret_cast<const float4*>(cb + (size_t)ks[tok] * DDIM)[c4];
        cbrow[tok][c4 * 4 + 0] = v.x;
        cbrow[tok][c4 * 4 + 1] = v.y;
        cbrow[tok][c4 * 4 + 2] = v.z;
        cbrow[tok][c4 * 4 + 3] = v.w;
    }
    __syncthreads();

    const size_t zbase = (size_t)b * DDIM * HW + p0;
    #pragma unroll
    for (int it = 0; it < 8; it++) {
        int slot = it * 256 + t;
        int d = slot >> 3, p4 = slot & 7;
        size_t off = zbase + (size_t)d * HW + p4 * 4;
        float4 zv = *reinterpret_cast<const float4*>(z + off);
        float q0 = cbrow[p4 * 4 + 0][d];
        float q1 = cbrow[p4 * 4 + 1][d];
        float q2 = cbrow[p4 * 4 + 2][d];
        float q3 = cbrow[p4 * 4 + 3][d];
        float4 r;
        r.x = __fadd_rn(zv.x, __fadd_rn(q0, -zv.x));   // STE chain (matched 7x)
        r.y = __fadd_rn(zv.y, __fadd_rn(q1, -zv.y));
        r.z = __fadd_rn(zv.z, __fadd_rn(q2, -zv.z));
        r.w = __fadd_rn(zv.w, __fadd_rn(q3, -zv.w));
        *reinterpret_cast<float4*>(out + off) = r;
    }
}

// ---------------------------------------------------------------------------
// mma stays launch #4 (profiler slot).
extern "C" void kernel_launch(void* const* d_in, const int* in_sizes, int n_in,
                              void* d_out, int out_size) {
    const float* z  = (const float*)d_in[0];
    const float* cb = (const float*)d_in[1];
    float* out = (float*)d_out;

    cudaFuncSetAttribute(mma_kernel,
                         cudaFuncAttributeMaxDynamicSharedMemorySize, MMA_SMEM);

    init_kernel<<<N_ROWS / 256, 256>>>();                              // 1
    cbcnorm_kernel<<<KCODES / 256, 256>>>(cb);                         // 2
    transpose_kernel<<<dim3(256, 16), 256>>>(z);                       // 3
    mma_kernel<<<dim3(N_ROWS / 128, KCODES / 128), 256, MMA_SMEM>>>(); // 4 <- profiled
    filter2_kernel<<<F2_GRID, 256>>>();                                // 5
    rescore_kernel<<<RS_GRID, 256>>>(cb);                              // 6
    gather_kernel<<<N_ROWS / GT, 256>>>(z, cb, out);                   // 7
}

// round 11
// speedup vs baseline: 6.1363x; 1.0990x over previous
#include <cuda_runtime.h>
#include <cuda_bf16.h>
#include <cstdint>

// Shapes (fixed): z (16,256,32,32) fp32; codebook (2048,256) fp32; out like z.
#define N_ROWS 16384
#define DDIM   256
#define KCODES 2048
#define HW     1024
#define CAND_CAP (1 << 22)   // 4M coarse candidates (expect ~870K)

// Margin: worst-case coarse error ~9e-4; 2.5e-3 validated in R7-R10.
#define MARGIN 2.5e-3f

// ---------------- device scratch (no mallocs allowed) ----------------
__device__ float              g_cnorm[KCODES];
__device__ uint32_t           g_minu[N_ROWS];
__device__ unsigned long long g_best[N_ROWS];
__device__ int                g_candCount;
__device__ unsigned long long g_cand[CAND_CAP];        // (coarse_bf16<<32)|(n<<11)|k
__device__ float              g_zt [N_ROWS * DDIM];    // token-major fp32 z
__device__ __nv_bfloat16      g_ztb[N_ROWS * DDIM];    // token-major bf16 z
__device__ __nv_bfloat16      g_cbb[KCODES * DDIM];    // bf16 codebook

// ---------------- small helpers ----------------
__device__ __forceinline__ uint32_t cvt_bf16x2(float a, float b) {  // lo=a, hi=b
    uint32_t r;
    asm("cvt.rn.bf16x2.f32 %0, %1, %2;" : "=r"(r) : "f"(b), "f"(a));
    return r;
}
__device__ __forceinline__ uint32_t fmap(float f) {
    uint32_t b = __float_as_uint(f);
    return (b & 0x80000000u) ? ~b : (b | 0x80000000u);
}
__device__ __forceinline__ float funmap(uint32_t u) {
    uint32_t b = (u & 0x80000000u) ? (u & 0x7fffffffu) : ~u;
    return __uint_as_float(b);
}
__device__ __forceinline__ void ldsm4(uint32_t& r0, uint32_t& r1, uint32_t& r2,
                                      uint32_t& r3, uint32_t addr) {
    asm volatile("ldmatrix.sync.aligned.m8n8.x4.shared.b16 {%0,%1,%2,%3}, [%4];"
                 : "=r"(r0), "=r"(r1), "=r"(r2), "=r"(r3) : "r"(addr));
}
__device__ __forceinline__ uint32_t smem_u32(const void* p) {
    uint32_t a;
    asm("{ .reg .u64 t; cvta.to.shared.u64 t, %1; cvt.u32.u64 %0, t; }" : "=r"(a) : "l"(p));
    return a;
}
__device__ __forceinline__ void mma16816(float* c, uint32_t a0, uint32_t a1,
                                         uint32_t a2, uint32_t a3,
                                         uint32_t b0, uint32_t b1) {
    asm volatile(
        "mma.sync.aligned.m16n8k16.row.col.f32.bf16.bf16.f32 "
        "{%0,%1,%2,%3}, {%4,%5,%6,%7}, {%8,%9}, {%0,%1,%2,%3};"
        : "+f"(c[0]), "+f"(c[1]), "+f"(c[2]), "+f"(c[3])
        : "r"(a0), "r"(a1), "r"(a2), "r"(a3), "r"(b0), "r"(b1));
}
__device__ __forceinline__ void cp16(uint32_t dst, const void* src) {
    asm volatile("cp.async.cg.shared.global [%0], [%1], 16;" :: "r"(dst), "l"(src));
}

// ---------------- (1) prep: transpose + init + cbcnorm, one launch ----------
// CTAs [0,4096): transpose; [4096,4160): init; [4160,4168): cbcnorm.
#define PREP_T_CTAS 4096
#define PREP_I_CTAS 64
#define PREP_GRID   (PREP_T_CTAS + PREP_I_CTAS + 8)

__global__ void __launch_bounds__(256) prep_kernel(const float* __restrict__ z,
                                                   const float* __restrict__ cb) {
    const int bx = blockIdx.x, t = threadIdx.x;
    if (bx < PREP_T_CTAS) {
        // --- transpose z -> token-major fp32 + bf16 (identical math to R10)
        __shared__ float ts[32][33];
        int tx = t & 31, ty = t >> 5;
        int idx = bx;
        int b  = idx >> 8;
        int rest = idx & 255;
        int pt = rest & 31, dt = rest >> 5;
        int p0 = pt * 32, d0 = dt * 32;
        #pragma unroll
        for (int i = 0; i < 4; i++) {
            int d = d0 + ty + i * 8;
            ts[ty + i * 8][tx] = z[((size_t)(b * DDIM + d)) * HW + p0 + tx];
        }
        __syncthreads();
        #pragma unroll
        for (int i = 0; i < 4; i++) {
            int n = b * HW + p0 + ty + i * 8;
            float v = ts[tx][ty + i * 8];
            g_zt [(size_t)n * DDIM + d0 + tx] = v;
            g_ztb[(size_t)n * DDIM + d0 + tx] = __float2bfloat16(v);
        }
    } else if (bx < PREP_T_CTAS + PREP_I_CTAS) {
        // --- init per-replay state
        int n = (bx - PREP_T_CTAS) * 256 + t;
        g_minu[n] = 0xFFFFFFFFu;
        g_best[n] = 0xFFFFFFFFFFFFFFFFull;
        if (n == 0) g_candCount = 0;
    } else {
        // --- codebook: bf16 convert + exact sequential cnorm (matched JAX 8x)
        int k = (bx - PREP_T_CTAS - PREP_I_CTAS) * 256 + t;
        const float4* row4 = reinterpret_cast<const float4*>(cb + (size_t)k * DDIM);
        uint32_t* out = reinterpret_cast<uint32_t*>(g_cbb + (size_t)k * DDIM);
        float s = 0.f;
        #pragma unroll 4
        for (int d4 = 0; d4 < DDIM / 4; d4++) {
            float4 v = row4[d4];
            s = __fmaf_rn(v.x, v.x, s);
            s = __fmaf_rn(v.y, v.y, s);
            s = __fmaf_rn(v.z, v.z, s);
            s = __fmaf_rn(v.w, v.w, s);
            out[d4 * 2 + 0] = cvt_bf16x2(v.x, v.y);
            out[d4 * 2 + 1] = cvt_bf16x2(v.z, v.w);
        }
        g_cnorm[k] = s;
    }
}

// ---------------- (2) coarse GEMM (cp.async double-buffered) + emission -----
// Byte-identical to R9/R10 (verified).
#define PITCH 72
#define A_BYTES (128 * PITCH * 2)
#define STAGE_BYTES (2 * A_BYTES)
#define MMA_SMEM (2 * STAGE_BYTES)       // 73728 dynamic

__global__ void __launch_bounds__(256, 2) mma_kernel() {
    extern __shared__ __align__(16) char dsm[];
    __shared__ int s_cnt, s_base;

    const int t = threadIdx.x, wid = t >> 5, lane = t & 31;
    const int row0 = blockIdx.x * 128, col0 = blockIdx.y * 128;
    const int wm = (wid & 3) * 32;
    const int wn = (wid >> 2) * 64;
    const int r  = lane >> 2, tt = lane & 3;
    const int grp = lane >> 3, l7 = lane & 7;

    const int a_row = (grp & 1) * 8 + l7, a_k = (grp & 2) * 4;
    const int b_row = (grp & 2) * 4 + l7, b_k = (grp & 1) * 8;
    const uint32_t sbase = smem_u32(dsm);
    uint32_t aOff[2], bOff[4];
    #pragma unroll
    for (int mt = 0; mt < 2; mt++)
        aOff[mt] = ((wm + mt * 16 + a_row) * PITCH + a_k) * 2;
    #pragma unroll
    for (int p = 0; p < 4; p++)
        bOff[p] = A_BYTES + ((wn + p * 16 + b_row) * PITCH + b_k) * 2;

    float acc[2][8][4];
    #pragma unroll
    for (int mt = 0; mt < 2; mt++)
        #pragma unroll
        for (int nt = 0; nt < 8; nt++)
            #pragma unroll
            for (int q = 0; q < 4; q++) acc[mt][nt][q] = 0.f;

    auto prefetch = [&](int ch) {
        const int s = ch & 1, cd0 = ch * 64;
        const uint32_t abuf = sbase + s * STAGE_BYTES;
        const uint32_t bbuf = abuf + A_BYTES;
        #pragma unroll
        for (int it = 0; it < 4; it++) {
            int idx = it * 256 + t;
            int rr = idx >> 3, k8 = (idx & 7) * 8;
            uint32_t off = (rr * PITCH + k8) * 2;
            cp16(abuf + off, &g_ztb[(size_t)(row0 + rr) * DDIM + cd0 + k8]);
            cp16(bbuf + off, &g_cbb[(size_t)(col0 + rr) * DDIM + cd0 + k8]);
        }
        asm volatile("cp.async.commit_group;" ::: "memory");
    };

    prefetch(0);
    for (int ch = 0; ch < 4; ch++) {
        if (ch < 3) {
            prefetch(ch + 1);
            asm volatile("cp.async.wait_group 1;" ::: "memory");
        } else {
            asm volatile("cp.async.wait_group 0;" ::: "memory");
        }
        __syncthreads();
        const uint32_t sb = sbase + (ch & 1) * STAGE_BYTES;
        #pragma unroll
        for (int ks = 0; ks < 4; ks++) {
            const uint32_t koff = ks * 32;
            uint32_t A0[4], A1[4];
            ldsm4(A0[0], A0[1], A0[2], A0[3], sb + aOff[0] + koff);
            ldsm4(A1[0], A1[1], A1[2], A1[3], sb + aOff[1] + koff);
            #pragma unroll
            for (int p = 0; p < 4; p++) {
                uint32_t B[4];
                ldsm4(B[0], B[1], B[2], B[3], sb + bOff[p] + koff);
                mma16816(acc[0][2 * p],     A0[0], A0[1], A0[2], A0[3], B[0], B[1]);
                mma16816(acc[0][2 * p + 1], A0[0], A0[1], A0[2], A0[3], B[2], B[3]);
                mma16816(acc[1][2 * p],     A1[0], A1[1], A1[2], A1[3], B[0], B[1]);
                mma16816(acc[1][2 * p + 1], A1[0], A1[1], A1[2], A1[3], B[2], B[3]);
            }
        }
        __syncthreads();
    }

    // --- epilogue: coarse = cnorm - 2*dot; warp row mins; emission ---
    float rmin[2][2];
    #pragma unroll
    for (int mt = 0; mt < 2; mt++) { rmin[mt][0] = 3.4e38f; rmin[mt][1] = 3.4e38f; }
    #pragma unroll
    for (int mt = 0; mt < 2; mt++)
        #pragma unroll
        for (int nt = 0; nt < 8; nt++) {
            const int cbase = col0 + wn + nt * 8;
            float2 cn = *reinterpret_cast<const float2*>(&g_cnorm[cbase + tt * 2]);
            float d0 = __fmaf_rn(-2.f, acc[mt][nt][0], cn.x);
            float d1 = __fmaf_rn(-2.f, acc[mt][nt][1], cn.y);
            float d2 = __fmaf_rn(-2.f, acc[mt][nt][2], cn.x);
            float d3 = __fmaf_rn(-2.f, acc[mt][nt][3], cn.y);
            acc[mt][nt][0] = d0; acc[mt][nt][1] = d1;
            acc[mt][nt][2] = d2; acc[mt][nt][3] = d3;
            rmin[mt][0] = fminf(rmin[mt][0], fminf(d0, d1));
            rmin[mt][1] = fminf(rmin[mt][1], fminf(d2, d3));
        }
    #pragma unroll
    for (int mt = 0; mt < 2; mt++)
        #pragma unroll
        for (int h = 0; h < 2; h++)
            #pragma unroll
            for (int off = 1; off < 4; off <<= 1)
                rmin[mt][h] = fminf(rmin[mt][h],
                                    __shfl_xor_sync(0xffffffffu, rmin[mt][h], off));

    float gmv[2][2];
    if (tt == 0) {
        #pragma unroll
        for (int mt = 0; mt < 2; mt++) {
            const int grow = row0 + wm + mt * 16 + r;
            uint32_t o0 = atomicMin(&g_minu[grow],     fmap(rmin[mt][0]));
            uint32_t o1 = atomicMin(&g_minu[grow + 8], fmap(rmin[mt][1]));
            gmv[mt][0] = funmap(o0);   // NaN if untouched; fminf ignores NaN
            gmv[mt][1] = funmap(o1);
        }
    }
    const int src = lane & ~3;
    float th[2][2];
    #pragma unroll
    for (int mt = 0; mt < 2; mt++)
        #pragma unroll
        for (int h = 0; h < 2; h++) {
            float g = __shfl_sync(0xffffffffu, gmv[mt][h], src);
            th[mt][h] = fminf(rmin[mt][h], g) + (MARGIN + 1e-4f);
        }

    if (t == 0) s_cnt = 0;
    int cnt = 0;
    #pragma unroll
    for (int mt = 0; mt < 2; mt++)
        #pragma unroll
        for (int nt = 0; nt < 8; nt++)
            #pragma unroll
            for (int q = 0; q < 4; q++)
                cnt += (acc[mt][nt][q] <= th[mt][q >> 1]) ? 1 : 0;

    int pref = cnt;
    #pragma unroll
    for (int off = 1; off < 32; off <<= 1) {
        int v = __shfl_up_sync(0xffffffffu, pref, off);
        if (lane >= off) pref += v;
    }
    int excl = pref - cnt;
    __syncthreads();
    int wbase = 0;
    if (lane == 31) wbase = atomicAdd(&s_cnt, pref);
    wbase = __shfl_sync(0xffffffffu, wbase, 31);
    __syncthreads();
    if (t == 0) s_base = s_cnt ? atomicAdd(&g_candCount, s_cnt) : 0;
    __syncthreads();
    int pos = s_base + wbase + excl;

    #pragma unroll
    for (int mt = 0; mt < 2; mt++)
        #pragma unroll
        for (int nt = 0; nt < 8; nt++)
            #pragma unroll
            for (int q = 0; q < 4; q++) {
                float d = acc[mt][nt][q];
                if (d <= th[mt][q >> 1]) {
                    if (pos < CAND_CAP) {
                        int grow = row0 + wm + mt * 16 + r + ((q >> 1) ? 8 : 0);
                        int k    = col0 + wn + nt * 8 + tt * 2 + (q & 1);
                        uint32_t dbits =
                            (uint32_t)__bfloat16_as_ushort(__float2bfloat16(d));
                        g_cand[pos] = ((unsigned long long)dbits << 32)
                                    | ((uint32_t)grow << 11) | (uint32_t)k;
                    }
                    pos++;
                }
            }
}

// ---------------- (3) rescore: inline global-margin filter + exact chain ----
// Grid-strides over g_cand directly (no compaction round-trip). Inactive
// lanes in a warp cost no extra issue, so sparse-pass warps are cheap.
#define RS_GRID 1024

__global__ void __launch_bounds__(256) rescore_kernel(const float* __restrict__ cb) {
    int total = g_candCount; if (total > CAND_CAP) total = CAND_CAP;
    for (int i = blockIdx.x * 256 + threadIdx.x; i < total; i += RS_GRID * 256) {
        unsigned long long e = g_cand[i];
        uint32_t nk = (uint32_t)e & 0x1FFFFFFu;
        int n = nk >> 11, k = nk & 2047;
        float coarse =
            __bfloat162float(__ushort_as_bfloat16((unsigned short)(e >> 32)));
        if (coarse <= funmap(g_minu[n]) + MARGIN) {
            const float4* za4 = reinterpret_cast<const float4*>(g_zt + (size_t)n * DDIM);
            const float4* ca4 = reinterpret_cast<const float4*>(cb + (size_t)k * DDIM);
            float acc = 0.f, zn = 0.f;
            #pragma unroll 8
            for (int d4 = 0; d4 < DDIM / 4; d4++) {
                float4 a = za4[d4], c = ca4[d4];
                zn  = __fmaf_rn(a.x, a.x, zn);    // znorm chain (verified 8x)
                zn  = __fmaf_rn(a.y, a.y, zn);
                zn  = __fmaf_rn(a.z, a.z, zn);
                zn  = __fmaf_rn(a.w, a.w, zn);
                acc = __fmaf_rn(a.x, c.x, acc);   // dot chain (verified 8x)
                acc = __fmaf_rn(a.y, c.y, acc);
                acc = __fmaf_rn(a.z, c.z, acc);
                acc = __fmaf_rn(a.w, c.w, acc);
            }
            float dist = __fadd_rn(__fadd_rn(zn, g_cnorm[k]), -2.0f * acc);
            unsigned long long pk =
                ((unsigned long long)__float_as_uint(dist) << 32) | (unsigned)k;
            atomicMin(&g_best[n], pk);
        }
    }
}

// ---------------- (4) gather + STE with smem-staged codebook rows ----------
#define GT 32   // tokens per CTA

__global__ void __launch_bounds__(256) gather_kernel(const float* __restrict__ z,
                                                     const float* __restrict__ cb,
                                                     float* __restrict__ out) {
    __shared__ float cbrow[GT][DDIM + 1];
    __shared__ int ks[GT];
    const int t = threadIdx.x;
    const int n0 = blockIdx.x * GT;
    const int b = n0 >> 10, p0 = n0 & 1023;

    if (t < GT) ks[t] = (int)(g_best[n0 + t] & 0xffffffffu);
    __syncthreads();

    #pragma unroll
    for (int it = 0; it < (GT * DDIM / 4) / 256; it++) {
        int slot = it * 256 + t;
        int tok = slot >> 6, c4 = slot & 63;
        float4 v = reinterpret_cast<const float4*>(cb + (size_t)ks[tok] * DDIM)[c4];
        cbrow[tok][c4 * 4 + 0] = v.x;
        cbrow[tok][c4 * 4 + 1] = v.y;
        cbrow[tok][c4 * 4 + 2] = v.z;
        cbrow[tok][c4 * 4 + 3] = v.w;
    }
    __syncthreads();

    const size_t zbase = (size_t)b * DDIM * HW + p0;
    #pragma unroll
    for (int it = 0; it < 8; it++) {
        int slot = it * 256 + t;
        int d = slot >> 3, p4 = slot & 7;
        size_t off = zbase + (size_t)d * HW + p4 * 4;
        float4 zv = *reinterpret_cast<const float4*>(z + off);
        float q0 = cbrow[p4 * 4 + 0][d];
        float q1 = cbrow[p4 * 4 + 1][d];
        float q2 = cbrow[p4 * 4 + 2][d];
        float q3 = cbrow[p4 * 4 + 3][d];
        float4 r;
        r.x = __fadd_rn(zv.x, __fadd_rn(q0, -zv.x));   // STE chain (matched 8x)
        r.y = __fadd_rn(zv.y, __fadd_rn(q1, -zv.y));
        r.z = __fadd_rn(zv.z, __fadd_rn(q2, -zv.z));
        r.w = __fadd_rn(zv.w, __fadd_rn(q3, -zv.w));
        *reinterpret_cast<float4*>(out + off) = r;
    }
}

// ---------------------------------------------------------------------------
extern "C" void kernel_launch(void* const* d_in, const int* in_sizes, int n_in,
                              void* d_out, int out_size) {
    const float* z  = (const float*)d_in[0];
    const float* cb = (const float*)d_in[1];
    float* out = (float*)d_out;

    cudaFuncSetAttribute(mma_kernel,
                         cudaFuncAttributeMaxDynamicSharedMemorySize, MMA_SMEM);

    prep_kernel<<<PREP_GRID, 256>>>(z, cb);                            // 1
    mma_kernel<<<dim3(N_ROWS / 128, KCODES / 128), 256, MMA_SMEM>>>(); // 2
    rescore_kernel<<<RS_GRID, 256>>>(cb);                              // 3
    gather_kernel<<<N_ROWS / GT, 256>>>(z, cb, out);                   // 4
}

// round 12
// speedup vs baseline: 6.1619x; 1.0042x over previous
#include <cuda_runtime.h>
#include <cuda_bf16.h>
#include <cstdint>

// Shapes (fixed): z (16,256,32,32) fp32; codebook (2048,256) fp32; out like z.
#define N_ROWS 16384
#define DDIM   256
#define KCODES 2048
#define HW     1024
#define CAND_CAP (1 << 22)   // 4M coarse candidates (expect ~870K)

// Margin: worst-case coarse error ~9e-4; 2.5e-3 validated in R7-R11.
#define MARGIN 2.5e-3f

// ---------------- device scratch (no mallocs allowed) ----------------
__device__ float              g_cnorm[KCODES];
__device__ uint32_t           g_minu[N_ROWS];
__device__ unsigned long long g_best[N_ROWS];
__device__ int                g_candCount;
__device__ unsigned long long g_cand[CAND_CAP];        // (coarse_bf16<<32)|(n<<11)|k
__device__ float              g_zt [N_ROWS * DDIM];    // token-major fp32 z
__device__ __nv_bfloat16      g_ztb[N_ROWS * DDIM];    // token-major bf16 z
__device__ __nv_bfloat16      g_cbb[KCODES * DDIM];    // bf16 codebook

// ---------------- small helpers ----------------
__device__ __forceinline__ uint32_t cvt_bf16x2(float a, float b) {  // lo=a, hi=b
    uint32_t r;
    asm("cvt.rn.bf16x2.f32 %0, %1, %2;" : "=r"(r) : "f"(b), "f"(a));
    return r;
}
__device__ __forceinline__ uint32_t fmap(float f) {
    uint32_t b = __float_as_uint(f);
    return (b & 0x80000000u) ? ~b : (b | 0x80000000u);
}
__device__ __forceinline__ float funmap(uint32_t u) {
    uint32_t b = (u & 0x80000000u) ? (u & 0x7fffffffu) : ~u;
    return __uint_as_float(b);
}
__device__ __forceinline__ void ldsm4(uint32_t& r0, uint32_t& r1, uint32_t& r2,
                                      uint32_t& r3, uint32_t addr) {
    asm volatile("ldmatrix.sync.aligned.m8n8.x4.shared.b16 {%0,%1,%2,%3}, [%4];"
                 : "=r"(r0), "=r"(r1), "=r"(r2), "=r"(r3) : "r"(addr));
}
__device__ __forceinline__ uint32_t smem_u32(const void* p) {
    uint32_t a;
    asm("{ .reg .u64 t; cvta.to.shared.u64 t, %1; cvt.u32.u64 %0, t; }" : "=r"(a) : "l"(p));
    return a;
}
__device__ __forceinline__ void mma16816(float* c, uint32_t a0, uint32_t a1,
                                         uint32_t a2, uint32_t a3,
                                         uint32_t b0, uint32_t b1) {
    asm volatile(
        "mma.sync.aligned.m16n8k16.row.col.f32.bf16.bf16.f32 "
        "{%0,%1,%2,%3}, {%4,%5,%6,%7}, {%8,%9}, {%0,%1,%2,%3};"
        : "+f"(c[0]), "+f"(c[1]), "+f"(c[2]), "+f"(c[3])
        : "r"(a0), "r"(a1), "r"(a2), "r"(a3), "r"(b0), "r"(b1));
}
__device__ __forceinline__ void cp16(uint32_t dst, const void* src) {
    asm volatile("cp.async.cg.shared.global [%0], [%1], 16;" :: "r"(dst), "l"(src));
}

// ---------------- (1) prep: transpose + init + cbcnorm, one launch ----------
#define PREP_T_CTAS 4096
#define PREP_I_CTAS 64
#define PREP_GRID   (PREP_T_CTAS + PREP_I_CTAS + 8)

__global__ void __launch_bounds__(256) prep_kernel(const float* __restrict__ z,
                                                   const float* __restrict__ cb) {
    const int bx = blockIdx.x, t = threadIdx.x;
    if (bx < PREP_T_CTAS) {
        __shared__ float ts[32][33];
        int tx = t & 31, ty = t >> 5;
        int b  = bx >> 8;
        int rest = bx & 255;
        int pt = rest & 31, dt = rest >> 5;
        int p0 = pt * 32, d0 = dt * 32;
        #pragma unroll
        for (int i = 0; i < 4; i++) {
            int d = d0 + ty + i * 8;
            ts[ty + i * 8][tx] = z[((size_t)(b * DDIM + d)) * HW + p0 + tx];
        }
        __syncthreads();
        #pragma unroll
        for (int i = 0; i < 4; i++) {
            int n = b * HW + p0 + ty + i * 8;
            float v = ts[tx][ty + i * 8];
            g_zt [(size_t)n * DDIM + d0 + tx] = v;
            g_ztb[(size_t)n * DDIM + d0 + tx] = __float2bfloat16(v);
        }
    } else if (bx < PREP_T_CTAS + PREP_I_CTAS) {
        int n = (bx - PREP_T_CTAS) * 256 + t;
        g_minu[n] = 0xFFFFFFFFu;
        g_best[n] = 0xFFFFFFFFFFFFFFFFull;
        if (n == 0) g_candCount = 0;
    } else {
        int k = (bx - PREP_T_CTAS - PREP_I_CTAS) * 256 + t;
        const float4* row4 = reinterpret_cast<const float4*>(cb + (size_t)k * DDIM);
        uint32_t* out = reinterpret_cast<uint32_t*>(g_cbb + (size_t)k * DDIM);
        float s = 0.f;
        #pragma unroll 4
        for (int d4 = 0; d4 < DDIM / 4; d4++) {
            float4 v = row4[d4];
            s = __fmaf_rn(v.x, v.x, s);   // sequential chain (matched JAX 9x)
            s = __fmaf_rn(v.y, v.y, s);
            s = __fmaf_rn(v.z, v.z, s);
            s = __fmaf_rn(v.w, v.w, s);
            out[d4 * 2 + 0] = cvt_bf16x2(v.x, v.y);
            out[d4 * 2 + 1] = cvt_bf16x2(v.z, v.w);
        }
        g_cnorm[k] = s;
    }
}

// ---------------- (2) coarse GEMM: 3-stage cp.async, 1 sync/chunk -----------
#define PITCH 72
#define A_BYTES (128 * PITCH * 2)        // 18432
#define STAGE_BYTES (2 * A_BYTES)        // 36864 (A + B per stage)
#define NSTAGE 3
#define MMA_SMEM (NSTAGE * STAGE_BYTES)  // 110592 dynamic

__global__ void __launch_bounds__(256, 2) mma_kernel() {
    extern __shared__ __align__(16) char dsm[];
    __shared__ int s_cnt, s_base;

    const int t = threadIdx.x, wid = t >> 5, lane = t & 31;
    const int row0 = blockIdx.x * 128, col0 = blockIdx.y * 128;
    const int wm = (wid & 3) * 32;
    const int wn = (wid >> 2) * 64;
    const int r  = lane >> 2, tt = lane & 3;
    const int grp = lane >> 3, l7 = lane & 7;

    const int a_row = (grp & 1) * 8 + l7, a_k = (grp & 2) * 4;
    const int b_row = (grp & 2) * 4 + l7, b_k = (grp & 1) * 8;
    const uint32_t sbase = smem_u32(dsm);
    uint32_t aOff[2], bOff[4];                   // stage-relative
    #pragma unroll
    for (int mt = 0; mt < 2; mt++)
        aOff[mt] = ((wm + mt * 16 + a_row) * PITCH + a_k) * 2;
    #pragma unroll
    for (int p = 0; p < 4; p++)
        bOff[p] = A_BYTES + ((wn + p * 16 + b_row) * PITCH + b_k) * 2;

    float acc[2][8][4];
    #pragma unroll
    for (int mt = 0; mt < 2; mt++)
        #pragma unroll
        for (int nt = 0; nt < 8; nt++)
            #pragma unroll
            for (int q = 0; q < 4; q++) acc[mt][nt][q] = 0.f;

    auto prefetch = [&](int ch) {
        const int s = ch % NSTAGE, cd0 = ch * 64;
        const uint32_t abuf = sbase + s * STAGE_BYTES;
        const uint32_t bbuf = abuf + A_BYTES;
        #pragma unroll
        for (int it = 0; it < 4; it++) {
            int idx = it * 256 + t;
            int rr = idx >> 3, k8 = (idx & 7) * 8;
            uint32_t off = (rr * PITCH + k8) * 2;
            cp16(abuf + off, &g_ztb[(size_t)(row0 + rr) * DDIM + cd0 + k8]);
            cp16(bbuf + off, &g_cbb[(size_t)(col0 + rr) * DDIM + cd0 + k8]);
        }
        asm volatile("cp.async.commit_group;" ::: "memory");
    };

    prefetch(0);
    prefetch(1);
    for (int ch = 0; ch < 4; ch++) {
        // chunk ch resident when <= (groups_in_flight - this one) remain
        if (ch < 3) asm volatile("cp.async.wait_group 1;" ::: "memory");
        else        asm volatile("cp.async.wait_group 0;" ::: "memory");
        __syncthreads();   // single barrier: aligns warps + publishes stage ch
        // prefetch ch+2 into stage (ch+2)%3: its last readers (chunk ch-1)
        // are all past the barrier above.
        if (ch < 2) prefetch(ch + 2);

        const uint32_t sb = sbase + (ch % NSTAGE) * STAGE_BYTES;
        #pragma unroll
        for (int ks = 0; ks < 4; ks++) {
            const uint32_t koff = ks * 32;
            uint32_t A0[4], A1[4];
            ldsm4(A0[0], A0[1], A0[2], A0[3], sb + aOff[0] + koff);
            ldsm4(A1[0], A1[1], A1[2], A1[3], sb + aOff[1] + koff);
            #pragma unroll
            for (int p = 0; p < 4; p++) {
                uint32_t B[4];
                ldsm4(B[0], B[1], B[2], B[3], sb + bOff[p] + koff);
                mma16816(acc[0][2 * p],     A0[0], A0[1], A0[2], A0[3], B[0], B[1]);
                mma16816(acc[0][2 * p + 1], A0[0], A0[1], A0[2], A0[3], B[2], B[3]);
                mma16816(acc[1][2 * p],     A1[0], A1[1], A1[2], A1[3], B[0], B[1]);
                mma16816(acc[1][2 * p + 1], A1[0], A1[1], A1[2], A1[3], B[2], B[3]);
            }
        }
    }
    __syncthreads();   // all compute done before smem reuse below (s_cnt etc.)

    // --- epilogue: coarse = cnorm - 2*dot; warp row mins; emission ---
    float rmin[2][2];
    #pragma unroll
    for (int mt = 0; mt < 2; mt++) { rmin[mt][0] = 3.4e38f; rmin[mt][1] = 3.4e38f; }
    #pragma unroll
    for (int mt = 0; mt < 2; mt++)
        #pragma unroll
        for (int nt = 0; nt < 8; nt++) {
            const int cbase = col0 + wn + nt * 8;
            float2 cn = *reinterpret_cast<const float2*>(&g_cnorm[cbase + tt * 2]);
            float d0 = __fmaf_rn(-2.f, acc[mt][nt][0], cn.x);
            float d1 = __fmaf_rn(-2.f, acc[mt][nt][1], cn.y);
            float d2 = __fmaf_rn(-2.f, acc[mt][nt][2], cn.x);
            float d3 = __fmaf_rn(-2.f, acc[mt][nt][3], cn.y);
            acc[mt][nt][0] = d0; acc[mt][nt][1] = d1;
            acc[mt][nt][2] = d2; acc[mt][nt][3] = d3;
            rmin[mt][0] = fminf(rmin[mt][0], fminf(d0, d1));
            rmin[mt][1] = fminf(rmin[mt][1], fminf(d2, d3));
        }
    #pragma unroll
    for (int mt = 0; mt < 2; mt++)
        #pragma unroll
        for (int h = 0; h < 2; h++)
            #pragma unroll
            for (int off = 1; off < 4; off <<= 1)
                rmin[mt][h] = fminf(rmin[mt][h],
                                    __shfl_xor_sync(0xffffffffu, rmin[mt][h], off));

    float gmv[2][2];
    if (tt == 0) {
        #pragma unroll
        for (int mt = 0; mt < 2; mt++) {
            const int grow = row0 + wm + mt * 16 + r;
            uint32_t o0 = atomicMin(&g_minu[grow],     fmap(rmin[mt][0]));
            uint32_t o1 = atomicMin(&g_minu[grow + 8], fmap(rmin[mt][1]));
            gmv[mt][0] = funmap(o0);   // NaN if untouched; fminf ignores NaN
            gmv[mt][1] = funmap(o1);
        }
    }
    const int src = lane & ~3;
    float th[2][2];
    #pragma unroll
    for (int mt = 0; mt < 2; mt++)
        #pragma unroll
        for (int h = 0; h < 2; h++) {
            float g = __shfl_sync(0xffffffffu, gmv[mt][h], src);
            th[mt][h] = fminf(rmin[mt][h], g) + (MARGIN + 1e-4f);
        }

    if (t == 0) s_cnt = 0;
    int cnt = 0;
    #pragma unroll
    for (int mt = 0; mt < 2; mt++)
        #pragma unroll
        for (int nt = 0; nt < 8; nt++)
            #pragma unroll
            for (int q = 0; q < 4; q++)
                cnt += (acc[mt][nt][q] <= th[mt][q >> 1]) ? 1 : 0;

    int pref = cnt;
    #pragma unroll
    for (int off = 1; off < 32; off <<= 1) {
        int v = __shfl_up_sync(0xffffffffu, pref, off);
        if (lane >= off) pref += v;
    }
    int excl = pref - cnt;
    __syncthreads();
    int wbase = 0;
    if (lane == 31) wbase = atomicAdd(&s_cnt, pref);
    wbase = __shfl_sync(0xffffffffu, wbase, 31);
    __syncthreads();
    if (t == 0) s_base = s_cnt ? atomicAdd(&g_candCount, s_cnt) : 0;
    __syncthreads();
    int pos = s_base + wbase + excl;

    #pragma unroll
    for (int mt = 0; mt < 2; mt++)
        #pragma unroll
        for (int nt = 0; nt < 8; nt++)
            #pragma unroll
            for (int q = 0; q < 4; q++) {
                float d = acc[mt][nt][q];
                if (d <= th[mt][q >> 1]) {
                    if (pos < CAND_CAP) {
                        int grow = row0 + wm + mt * 16 + r + ((q >> 1) ? 8 : 0);
                        int k    = col0 + wn + nt * 8 + tt * 2 + (q & 1);
                        uint32_t dbits =
                            (uint32_t)__bfloat16_as_ushort(__float2bfloat16(d));
                        g_cand[pos] = ((unsigned long long)dbits << 32)
                                    | ((uint32_t)grow << 11) | (uint32_t)k;
                    }
                    pos++;
                }
            }
}

// ---------------- (3) rescore: inline filter + exact chain (as R11) ---------
#define RS_GRID 1024

__global__ void __launch_bounds__(256) rescore_kernel(const float* __restrict__ cb) {
    int total = g_candCount; if (total > CAND_CAP) total = CAND_CAP;
    for (int i = blockIdx.x * 256 + threadIdx.x; i < total; i += RS_GRID * 256) {
        unsigned long long e = g_cand[i];
        uint32_t nk = (uint32_t)e & 0x1FFFFFFu;
        int n = nk >> 11, k = nk & 2047;
        float coarse =
            __bfloat162float(__ushort_as_bfloat16((unsigned short)(e >> 32)));
        if (coarse <= funmap(g_minu[n]) + MARGIN) {
            const float4* za4 = reinterpret_cast<const float4*>(g_zt + (size_t)n * DDIM);
            const float4* ca4 = reinterpret_cast<const float4*>(cb + (size_t)k * DDIM);
            float acc = 0.f, zn = 0.f;
            #pragma unroll 8
            for (int d4 = 0; d4 < DDIM / 4; d4++) {
                float4 a = za4[d4], c = ca4[d4];
                zn  = __fmaf_rn(a.x, a.x, zn);    // znorm chain (verified 9x)
                zn  = __fmaf_rn(a.y, a.y, zn);
                zn  = __fmaf_rn(a.z, a.z, zn);
                zn  = __fmaf_rn(a.w, a.w, zn);
                acc = __fmaf_rn(a.x, c.x, acc);   // dot chain (verified 9x)
                acc = __fmaf_rn(a.y, c.y, acc);
                acc = __fmaf_rn(a.z, c.z, acc);
                acc = __fmaf_rn(a.w, c.w, acc);
            }
            float dist = __fadd_rn(__fadd_rn(zn, g_cnorm[k]), -2.0f * acc);
            unsigned long long pk =
                ((unsigned long long)__float_as_uint(dist) << 32) | (unsigned)k;
            atomicMin(&g_best[n], pk);
        }
    }
}

// ---------------- (4) gather + STE with smem-staged codebook rows ----------
#define GT 32   // tokens per CTA

__global__ void __launch_bounds__(256) gather_kernel(const float* __restrict__ z,
                                                     const float* __restrict__ cb,
                                                     float* __restrict__ out) {
    __shared__ float cbrow[GT][DDIM + 1];
    __shared__ int ks[GT];
    const int t = threadIdx.x;
    const int n0 = blockIdx.x * GT;
    const int b = n0 >> 10, p0 = n0 & 1023;

    if (t < GT) ks[t] = (int)(g_best[n0 + t] & 0xffffffffu);
    __syncthreads();

    #pragma unroll
    for (int it = 0; it < (GT * DDIM / 4) / 256; it++) {
        int slot = it * 256 + t;
        int tok = slot >> 6, c4 = slot & 63;
        float4 v = reinterpret_cast<const float4*>(cb + (size_t)ks[tok] * DDIM)[c4];
        cbrow[tok][c4 * 4 + 0] = v.x;
        cbrow[tok][c4 * 4 + 1] = v.y;
        cbrow[tok][c4 * 4 + 2] = v.z;
        cbrow[tok][c4 * 4 + 3] = v.w;
    }
    __syncthreads();

    const size_t zbase = (size_t)b * DDIM * HW + p0;
    #pragma unroll
    for (int it = 0; it < 8; it++) {
        int slot = it * 256 + t;
        int d = slot >> 3, p4 = slot & 7;
        size_t off = zbase + (size_t)d * HW + p4 * 4;
        float4 zv = *reinterpret_cast<const float4*>(z + off);
        float q0 = cbrow[p4 * 4 + 0][d];
        float q1 = cbrow[p4 * 4 + 1][d];
        float q2 = cbrow[p4 * 4 + 2][d];
        float q3 = cbrow[p4 * 4 + 3][d];
        float4 r;
        r.x = __fadd_rn(zv.x, __fadd_rn(q0, -zv.x));   // STE chain (matched 9x)
        r.y = __fadd_rn(zv.y, __fadd_rn(q1, -zv.y));
        r.z = __fadd_rn(zv.z, __fadd_rn(q2, -zv.z));
        r.w = __fadd_rn(zv.w, __fadd_rn(q3, -zv.w));
        *reinterpret_cast<float4*>(out + off) = r;
    }
}

// ---------------------------------------------------------------------------
extern "C" void kernel_launch(void* const* d_in, const int* in_sizes, int n_in,
                              void* d_out, int out_size) {
    const float* z  = (const float*)d_in[0];
    const float* cb = (const float*)d_in[1];
    float* out = (float*)d_out;

    cudaFuncSetAttribute(mma_kernel,
                         cudaFuncAttributeMaxDynamicSharedMemorySize, MMA_SMEM);

    prep_kernel<<<PREP_GRID, 256>>>(z, cb);                            // 1
    mma_kernel<<<dim3(N_ROWS / 128, KCODES / 128), 256, MMA_SMEM>>>(); // 2
    rescore_kernel<<<RS_GRID, 256>>>(cb);                              // 3
    gather_kernel<<<N_ROWS / GT, 256>>>(z, cb, out);                   // 4
}